// round 6
// baseline (speedup 1.0000x reference)
#include <cuda_runtime.h>
#include <cuda_fp16.h>
#include <math.h>

#define NN 50000
#define EE 800000
#define CLS 128

// ---------------- static device scratch ----------------
__device__ __half g_t [NN * 256];
__device__ __half g_u [NN * 128];
__device__ float g_res[NN * 64];
__device__ float g_h1[NN * 128];
__device__ float g_h2[NN * 64];
__device__ float4 g_blob0[16384];   // layer0 weights K=128,N=256, frag order, hi/lo
__device__ float4 g_blob1[12288];   // layer1 weights K=128,N=192 (incl res), frag order
__device__ float g_bsum[448];
__device__ int   g_deg_in[NN];
__device__ int   g_deg_out[NN];
__device__ int   g_rp_in[NN + 1];
__device__ int   g_rp_out[NN + 1];
__device__ int   g_cur_in[NN];
__device__ int   g_cur_out[NN];
__device__ int2  g_edge_in[EE];     // packed (src, weight bits)
__device__ int2  g_edge_out[EE];
__device__ int   g_is64;

// ---------------- tf32 helpers ----------------
__device__ __forceinline__ void split_tf32(float a, unsigned& hi, unsigned& lo) {
    asm("cvt.rna.tf32.f32 %0, %1;" : "=r"(hi) : "f"(a));
    float r = a - __uint_as_float(hi);
    asm("cvt.rna.tf32.f32 %0, %1;" : "=r"(lo) : "f"(r));
}

__device__ __forceinline__ void mma_tf32(float4& d,
    unsigned a0, unsigned a1, unsigned a2, unsigned a3,
    unsigned b0, unsigned b1)
{
    asm volatile(
        "mma.sync.aligned.m16n8k8.row.col.f32.tf32.tf32.f32 "
        "{%0,%1,%2,%3},{%4,%5,%6,%7},{%8,%9},{%0,%1,%2,%3};"
        : "+f"(d.x), "+f"(d.y), "+f"(d.z), "+f"(d.w)
        : "r"(a0), "r"(a1), "r"(a2), "r"(a3), "r"(b0), "r"(b1));
}

__device__ __forceinline__ void cp16(void* smem_dst, const void* gsrc, int sz) {
    unsigned du = (unsigned)__cvta_generic_to_shared(smem_dst);
    asm volatile("cp.async.cg.shared.global [%0], [%1], 16, %2;"
                 :: "r"(du), "l"(gsrc), "r"(sz));
}

// ---------------- misc small kernels ----------------
__global__ void detect_kernel(const int* __restrict__ ei, int* __restrict__ da,
                              int* __restrict__ db, int n) {
    if (blockIdx.x == 0 && threadIdx.x == 0) {
        int z = 0;
        for (int i = 1; i < 129; i += 2) z |= ei[i];
        g_is64 = (z == 0) ? 1 : 0;
    }
    int i = blockIdx.x * blockDim.x + threadIdx.x;
    if (i < n) { da[i] = 0; db[i] = 0; }
}

// build frag-ordered, hi/lo-split weight blobs + combined biases
__global__ void prep_kernel(
    const float* __restrict__ Wmi0, const float* __restrict__ Wmo0, const float* __restrict__ Ws0,
    const float* __restrict__ Wmi1, const float* __restrict__ Wmo1, const float* __restrict__ Ws1,
    const float* __restrict__ resW,
    const float* __restrict__ bmi0, const float* __restrict__ bsi0,
    const float* __restrict__ bmo0, const float* __restrict__ bso0,
    const float* __restrict__ bmi1, const float* __restrict__ bsi1,
    const float* __restrict__ bmo1, const float* __restrict__ bso1,
    const float* __restrict__ resb,
    float4* __restrict__ blob0, float4* __restrict__ blob1, float* __restrict__ bsum)
{
    int i = blockIdx.x * blockDim.x + threadIdx.x;
    if (i < 16384) {
        int lane = i & 31; int j = i >> 5;
        int nt = j & 7; j >>= 3;
        int ks = j & 15; j >>= 4;
        int nc = j;
        int n = nc * 64 + nt * 8 + (lane >> 2);
        int ka = ks * 8 + (lane & 3), kb = ka + 4;
        int nn = n & 127;
        float a = Ws0[ka * 128 + nn] + ((n < 128) ? Wmi0[ka * 128 + n] : Wmo0[ka * 128 + n - 128]);
        float b = Ws0[kb * 128 + nn] + ((n < 128) ? Wmi0[kb * 128 + n] : Wmo0[kb * 128 + n - 128]);
        unsigned ha, la, hb, lb;
        split_tf32(a, ha, la); split_tf32(b, hb, lb);
        blob0[i] = make_float4(__uint_as_float(ha), __uint_as_float(hb),
                               __uint_as_float(la), __uint_as_float(lb));
        return;
    }
    int i1 = i - 16384;
    if (i1 < 12288) {
        int lane = i1 & 31; int j = i1 >> 5;
        int nt = j & 7; j >>= 3;
        int ks = j & 15; j >>= 4;
        int nc = j;
        int n = nc * 64 + nt * 8 + (lane >> 2);
        int ka = ks * 8 + (lane & 3), kb = ka + 4;
        float a, b;
        if (n < 128) {
            int nn = n & 63;
            a = Ws1[ka * 64 + nn] + ((n < 64) ? Wmi1[ka * 64 + n] : Wmo1[ka * 64 + n - 64]);
            b = Ws1[kb * 64 + nn] + ((n < 64) ? Wmi1[kb * 64 + n] : Wmo1[kb * 64 + n - 64]);
        } else {
            a = resW[ka * 64 + n - 128];
            b = resW[kb * 64 + n - 128];
        }
        unsigned ha, la, hb, lb;
        split_tf32(a, ha, la); split_tf32(b, hb, lb);
        blob1[i1] = make_float4(__uint_as_float(ha), __uint_as_float(hb),
                                __uint_as_float(la), __uint_as_float(lb));
        return;
    }
    int i2 = i1 - 12288;
    if (i2 < 128)       bsum[i2] = bmi0[i2] + bsi0[i2];
    else if (i2 < 256)  bsum[i2] = bmo0[i2 - 128] + bso0[i2 - 128];
    else if (i2 < 320)  bsum[i2] = bmi1[i2 - 256] + bsi1[i2 - 256];
    else if (i2 < 384)  bsum[i2] = bmo1[i2 - 320] + bso1[i2 - 320];
    else if (i2 < 448)  bsum[i2] = resb[i2 - 384];
}

// ---------------- CSR build (per-set, two streams) ----------------
__global__ void count_kernel(const int* __restrict__ ei, int* __restrict__ deg, int E) {
    int e = blockIdx.x * blockDim.x + threadIdx.x;
    if (e >= E) return;
    int tgt;
    if (g_is64) tgt = (int)((const long long*)ei)[E + e];
    else        tgt = ei[E + e];
    atomicAdd(deg + tgt, 1);
}

__global__ __launch_bounds__(1024) void scan1_kernel(
    const int* __restrict__ deg, int* __restrict__ rp, int* __restrict__ cur, int n)
{
    __shared__ int wsum[32];
    int tid = threadIdx.x, lane = tid & 31, wid = tid >> 5;
    int carry = 0;
    for (int base = 0; base < n; base += 1024) {
        int i = base + tid;
        int x = (i < n) ? deg[i] : 0;
        int v = x;
#pragma unroll
        for (int off = 1; off < 32; off <<= 1) {
            int t = __shfl_up_sync(0xffffffffu, v, off);
            if (lane >= off) v += t;
        }
        if (lane == 31) wsum[wid] = v;
        __syncthreads();
        if (wid == 0) {
            int w = wsum[lane];
#pragma unroll
            for (int off = 1; off < 32; off <<= 1) {
                int t = __shfl_up_sync(0xffffffffu, w, off);
                if (lane >= off) w += t;
            }
            wsum[lane] = w;
        }
        __syncthreads();
        int woff = wid ? wsum[wid - 1] : 0;
        int total = wsum[31];
        if (i < n) {
            int excl = carry + woff + v - x;
            rp[i] = excl;
            cur[i] = excl;
        }
        carry += total;
        __syncthreads();
    }
    if (tid == 0) rp[n] = carry;
}

__global__ void scatter_kernel(const int* __restrict__ ei, const float* __restrict__ ew,
                               int* __restrict__ cur, int2* __restrict__ edge, int E)
{
    int e = blockIdx.x * blockDim.x + threadIdx.x;
    if (e >= E) return;
    int src, tgt;
    if (g_is64) {
        const long long* p = (const long long*)ei;
        src = (int)p[e]; tgt = (int)p[E + e];
    } else {
        src = ei[e]; tgt = ei[E + e];
    }
    int pos = atomicAdd(cur + tgt, 1);
    edge[pos] = make_int2(src, __float_as_int(ew[e]));
}

// ---------------- tensor-core GEMM: (H (+pe)) @ W -------------------------
// fp16 output for the first HC cols (edge-gathered), fp32 for cols >= HC (residual).
template<int N, int HC, bool ADD_PE>
__global__ __launch_bounds__(256) void tgemm_kernel(
    const float* __restrict__ H, const float* __restrict__ pe,
    const float4* __restrict__ Wblob, __half* __restrict__ outH,
    float* __restrict__ outF, int nrows)
{
    constexpr int K = 128;
    constexpr int CHUNKS = N / 64;
    constexpr int AST = K + 4;
    extern __shared__ float smem[];
    float* shA  = smem;
    float* shB0 = smem + 128 * AST;
    float* shB1 = shB0 + 16384;

    const int tid  = threadIdx.x;
    const int lane = tid & 31;
    const int wm   = (tid >> 5) * 16;
    const int g    = lane >> 2;
    const int row0 = blockIdx.x * 128;

#pragma unroll
    for (int i = 0; i < 16; i++) {
        int lin = tid + 256 * i;
        int r = lin >> 5, c4 = (lin & 31) << 2;
        int sz = (row0 + r < nrows) ? 16 : 0;
        cp16(shA + r * AST + c4, H + (size_t)(row0 + r) * K + c4, sz);
    }
#pragma unroll
    for (int i = 0; i < 16; i++) {
        int lin = tid + 256 * i;
        cp16(shB0 + lin * 4, Wblob + lin, 16);
    }
    asm volatile("cp.async.commit_group;");
    asm volatile("cp.async.wait_group 0;");
    __syncthreads();

    if (ADD_PE) {
        int c4 = (tid & 31) << 2;
        float4 pv = *reinterpret_cast<const float4*>(pe + c4);
#pragma unroll
        for (int i = 0; i < 16; i++) {
            int r = (tid + 256 * i) >> 5;
            float4 v = *reinterpret_cast<float4*>(shA + r * AST + c4);
            v.x += pv.x; v.y += pv.y; v.z += pv.z; v.w += pv.w;
            *reinterpret_cast<float4*>(shA + r * AST + c4) = v;
        }
        __syncthreads();
    }

    for (int c = 0; c < CHUNKS; c++) {
        if (c + 1 < CHUNKS) {
            float* nb = ((c + 1) & 1) ? shB1 : shB0;
            const float4* src = Wblob + (size_t)(c + 1) * 4096;
#pragma unroll
            for (int i = 0; i < 16; i++) {
                int lin = tid + 256 * i;
                cp16(nb + lin * 4, src + lin, 16);
            }
            asm volatile("cp.async.commit_group;");
        }

        const float* shB = (c & 1) ? shB1 : shB0;
        float4 acc[8];
#pragma unroll
        for (int nt = 0; nt < 8; nt++) acc[nt] = make_float4(0.f, 0.f, 0.f, 0.f);

#pragma unroll 2
        for (int ks = 0; ks < 16; ks++) {
            int ka = ks * 8 + (lane & 3);
            const float* ap = shA + (wm + g) * AST + ka;
            float a0 = ap[0], a2 = ap[4];
            float a1 = ap[8 * AST], a3 = ap[8 * AST + 4];
            unsigned h0, l0, h1, l1, h2, l2, h3, l3;
            split_tf32(a0, h0, l0); split_tf32(a1, h1, l1);
            split_tf32(a2, h2, l2); split_tf32(a3, h3, l3);
            const uint4* bp = reinterpret_cast<const uint4*>(shB) + ks * 256 + lane;
#pragma unroll
            for (int nt = 0; nt < 8; nt++) {
                uint4 b = bp[nt * 32];
                mma_tf32(acc[nt], h0, h1, h2, h3, b.x, b.y);
                mma_tf32(acc[nt], h0, h1, h2, h3, b.z, b.w);
                mma_tf32(acc[nt], l0, l1, l2, l3, b.x, b.y);
            }
        }

        int r1 = row0 + wm + g, r2 = r1 + 8;
        int colb = c * 64 + 2 * (lane & 3);
        if (colb < HC) {
#pragma unroll
            for (int nt = 0; nt < 8; nt++) {
                int col = colb + nt * 8;
                if (r1 < nrows)
                    *reinterpret_cast<__half2*>(outH + (size_t)r1 * HC + col) =
                        __floats2half2_rn(acc[nt].x, acc[nt].y);
                if (r2 < nrows)
                    *reinterpret_cast<__half2*>(outH + (size_t)r2 * HC + col) =
                        __floats2half2_rn(acc[nt].z, acc[nt].w);
            }
        } else {
#pragma unroll
            for (int nt = 0; nt < 8; nt++) {
                int col = colb - HC + nt * 8;
                if (r1 < nrows)
                    *reinterpret_cast<float2*>(outF + (size_t)r1 * (N - HC) + col) =
                        make_float2(acc[nt].x, acc[nt].y);
                if (r2 < nrows)
                    *reinterpret_cast<float2*>(outF + (size_t)r2 * (N - HC) + col) =
                        make_float2(acc[nt].z, acc[nt].w);
            }
        }

        asm volatile("cp.async.wait_group 0;");
        __syncthreads();
    }
}

// ---------------- layer-0 gather+combine: warp per node (fp16 t) -----------
__global__ __launch_bounds__(256) void gather0_kernel(
    const __half* __restrict__ t,
    const int* __restrict__ rpi, const int2* __restrict__ egi,
    const int* __restrict__ rpo, const int2* __restrict__ ego,
    const float* __restrict__ bsum,
    const float* __restrict__ cin, const float* __restrict__ cout,
    const float* __restrict__ x, const float* __restrict__ pe,
    float* __restrict__ h1, int n)
{
    int node = (blockIdx.x * 256 + threadIdx.x) >> 5;
    int lane = threadIdx.x & 31;
    if (node >= n) return;

    float4 ic = make_float4(0.f, 0.f, 0.f, 0.f);
    float4 oc = make_float4(0.f, 0.f, 0.f, 0.f);

    int s = rpi[node], e = rpi[node + 1];
#pragma unroll 4
    for (int k = s; k < e; k++) {
        int2 ed = __ldg(egi + k);
        float w = __int_as_float(ed.y);
        float2 raw = *reinterpret_cast<const float2*>(t + (size_t)ed.x * 256 + lane * 4);
        float2 a = __half22float2(*reinterpret_cast<const __half2*>(&raw.x));
        float2 b = __half22float2(*reinterpret_cast<const __half2*>(&raw.y));
        ic.x += w * a.x; ic.y += w * a.y; ic.z += w * b.x; ic.w += w * b.y;
    }
    s = rpo[node]; e = rpo[node + 1];
#pragma unroll 4
    for (int k = s; k < e; k++) {
        int2 ed = __ldg(ego + k);
        float w = __int_as_float(ed.y);
        float2 raw = *reinterpret_cast<const float2*>(t + (size_t)ed.x * 256 + 128 + lane * 4);
        float2 a = __half22float2(*reinterpret_cast<const __half2*>(&raw.x));
        float2 b = __half22float2(*reinterpret_cast<const __half2*>(&raw.y));
        oc.x += w * a.x; oc.y += w * a.y; oc.z += w * b.x; oc.w += w * b.y;
    }

    float ci = __ldg(cin + node), co = __ldg(cout + node);
    float4 bi = *reinterpret_cast<const float4*>(bsum + lane * 4);
    float4 bo = *reinterpret_cast<const float4*>(bsum + 128 + lane * 4);
    float4 r  = *reinterpret_cast<const float4*>(x + (size_t)node * 128 + lane * 4);
    float4 pv = *reinterpret_cast<const float4*>(pe + lane * 4);
    r.x += pv.x; r.y += pv.y; r.z += pv.z; r.w += pv.w;
    float4 o;
    o.x = tanhf(ci * (ic.x + bi.x) + co * (oc.x + bo.x) + r.x);
    o.y = tanhf(ci * (ic.y + bi.y) + co * (oc.y + bo.y) + r.y);
    o.z = tanhf(ci * (ic.z + bi.z) + co * (oc.z + bo.z) + r.z);
    o.w = tanhf(ci * (ic.w + bi.w) + co * (oc.w + bo.w) + r.w);
    *reinterpret_cast<float4*>(h1 + (size_t)node * 128 + lane * 4) = o;
}

// ---------------- layer-1 gather+combine (fp16 u stride 128, fp32 res) -----
__global__ __launch_bounds__(256) void gather1_kernel(
    const __half* __restrict__ u, const float* __restrict__ res,
    const int* __restrict__ rpi, const int2* __restrict__ egi,
    const int* __restrict__ rpo, const int2* __restrict__ ego,
    const float* __restrict__ bsum,
    const float* __restrict__ cin, const float* __restrict__ cout,
    float* __restrict__ h2, int n)
{
    int node = (blockIdx.x * 256 + threadIdx.x) >> 5;
    int lane = threadIdx.x & 31;
    if (node >= n) return;

    float2 ic = make_float2(0.f, 0.f);
    float2 oc = make_float2(0.f, 0.f);

    int s = rpi[node], e = rpi[node + 1];
#pragma unroll 4
    for (int k = s; k < e; k++) {
        int2 ed = __ldg(egi + k);
        float w = __int_as_float(ed.y);
        float2 v = __half22float2(*reinterpret_cast<const __half2*>(u + (size_t)ed.x * 128 + lane * 2));
        ic.x += w * v.x; ic.y += w * v.y;
    }
    s = rpo[node]; e = rpo[node + 1];
#pragma unroll 4
    for (int k = s; k < e; k++) {
        int2 ed = __ldg(ego + k);
        float w = __int_as_float(ed.y);
        float2 v = __half22float2(*reinterpret_cast<const __half2*>(u + (size_t)ed.x * 128 + 64 + lane * 2));
        oc.x += w * v.x; oc.y += w * v.y;
    }

    float ci = __ldg(cin + node), co = __ldg(cout + node);
    float2 bi = *reinterpret_cast<const float2*>(bsum + 256 + lane * 2);
    float2 bo = *reinterpret_cast<const float2*>(bsum + 320 + lane * 2);
    float2 rb = *reinterpret_cast<const float2*>(bsum + 384 + lane * 2);
    float2 r  = *reinterpret_cast<const float2*>(res + (size_t)node * 64 + lane * 2);
    float2 o;
    o.x = tanhf(ci * (ic.x + bi.x) + co * (oc.x + bo.x) + r.x + rb.x);
    o.y = tanhf(ci * (ic.y + bi.y) + co * (oc.y + bo.y) + r.y + rb.y);
    *reinterpret_cast<float2*>(h2 + (size_t)node * 64 + lane * 2) = o;
}

// ---------------- decoder: warp handles 2 nodes -----------------------------
__device__ __forceinline__ void logsm_store(float4 acc, int node, int lane,
                                            float* __restrict__ logp, int n) {
    float m = fmaxf(fmaxf(acc.x, acc.y), fmaxf(acc.z, acc.w));
#pragma unroll
    for (int off = 16; off > 0; off >>= 1)
        m = fmaxf(m, __shfl_xor_sync(0xffffffffu, m, off));
    float s = expf(acc.x - m) + expf(acc.y - m) + expf(acc.z - m) + expf(acc.w - m);
#pragma unroll
    for (int off = 16; off > 0; off >>= 1)
        s += __shfl_xor_sync(0xffffffffu, s, off);
    float lse = m + logf(s);
    if (node < n) {
        float4 o = make_float4(acc.x - lse, acc.y - lse, acc.z - lse, acc.w - lse);
        *reinterpret_cast<float4*>(logp + (size_t)node * CLS + lane * 4) = o;
    }
}

__device__ __forceinline__ void emb_store(const float* __restrict__ h, int node, int lane,
                                          float* __restrict__ emb, int n) {
    float2 v = *reinterpret_cast<const float2*>(h + lane * 2);
    float sq = v.x * v.x + v.y * v.y;
#pragma unroll
    for (int off = 16; off > 0; off >>= 1)
        sq += __shfl_xor_sync(0xffffffffu, sq, off);
    float inv = 1.f / (sqrtf(sq) + 1e-12f);
    if (node < n) {
        float2 o = make_float2(v.x * inv, v.y * inv);
        *reinterpret_cast<float2*>(emb + (size_t)node * 64 + lane * 2) = o;
    }
}

__global__ __launch_bounds__(256) void decoder_kernel(
    const float* __restrict__ h2, const float* __restrict__ W,
    const float* __restrict__ b, float* __restrict__ logp,
    float* __restrict__ emb, int n)
{
    __shared__ float sh[16 * 64];
    int tid = threadIdx.x;
    int node0 = blockIdx.x * 16;

    for (int i = tid; i < 16 * 64; i += 256) {
        int nd = node0 + (i >> 6);
        sh[i] = (nd < n) ? h2[(size_t)nd * 64 + (i & 63)] : 0.f;
    }
    __syncthreads();

    int wid = tid >> 5, lane = tid & 31;
    int la = wid * 2, lb = la + 1;
    const float* ha = sh + la * 64;
    const float* hb = sh + lb * 64;

    float4 bj = *reinterpret_cast<const float4*>(b + lane * 4);
    float4 acc0 = bj, acc1 = bj;

#pragma unroll 4
    for (int k = 0; k < 64; k++) {
        float4 w = *reinterpret_cast<const float4*>(W + (size_t)k * CLS + lane * 4);
        float a = ha[k], c = hb[k];
        acc0.x += a * w.x; acc0.y += a * w.y; acc0.z += a * w.z; acc0.w += a * w.w;
        acc1.x += c * w.x; acc1.y += c * w.y; acc1.z += c * w.z; acc1.w += c * w.w;
    }

    logsm_store(acc0, node0 + la, lane, logp, n);
    logsm_store(acc1, node0 + lb, lane, logp, n);
    emb_store(ha, node0 + la, lane, emb, n);
    emb_store(hb, node0 + lb, lane, emb, n);
}

// ---------------- host ----------------
extern "C" void kernel_launch(void* const* d_in, const int* in_sizes, int n_in,
                              void* d_out, int out_size)
{
    const float* x      = (const float*)d_in[0];
    const int*   ei_in  = (const int*)d_in[1];
    const float* ew_in  = (const float*)d_in[2];
    const int*   ei_out = (const int*)d_in[3];
    const float* ew_out = (const float*)d_in[4];
    const float* pe     = (const float*)d_in[5];

    const float* Wmi0 = (const float*)d_in[6];
    const float* Wmo0 = (const float*)d_in[7];
    const float* Ws0  = (const float*)d_in[8];
    const float* bmi0 = (const float*)d_in[9];
    const float* bmo0 = (const float*)d_in[10];
    const float* bsi0 = (const float*)d_in[11];
    const float* bso0 = (const float*)d_in[12];
    const float* cin0 = (const float*)d_in[13];
    const float* cout0= (const float*)d_in[14];

    const float* Wmi1 = (const float*)d_in[15];
    const float* Wmo1 = (const float*)d_in[16];
    const float* Ws1  = (const float*)d_in[17];
    const float* bmi1 = (const float*)d_in[18];
    const float* bmo1 = (const float*)d_in[19];
    const float* bsi1 = (const float*)d_in[20];
    const float* bso1 = (const float*)d_in[21];
    const float* cin1 = (const float*)d_in[22];
    const float* cout1= (const float*)d_in[23];

    const float* resW = (const float*)d_in[24];
    const float* resb = (const float*)d_in[25];
    const float* decW = (const float*)d_in[26];
    const float* decb = (const float*)d_in[27];

    __half *t, *u;
    float *res, *h1, *h2, *bsum;
    float4 *blob0, *blob1;
    int *deg_in, *deg_out, *rp_in, *rp_out, *cur_in, *cur_out;
    int2 *edge_in, *edge_out;
    cudaGetSymbolAddress((void**)&t,   g_t);
    cudaGetSymbolAddress((void**)&u,   g_u);
    cudaGetSymbolAddress((void**)&res, g_res);
    cudaGetSymbolAddress((void**)&h1,  g_h1);
    cudaGetSymbolAddress((void**)&h2,  g_h2);
    cudaGetSymbolAddress((void**)&blob0, g_blob0);
    cudaGetSymbolAddress((void**)&blob1, g_blob1);
    cudaGetSymbolAddress((void**)&bsum,g_bsum);
    cudaGetSymbolAddress((void**)&deg_in,  g_deg_in);
    cudaGetSymbolAddress((void**)&deg_out, g_deg_out);
    cudaGetSymbolAddress((void**)&rp_in,   g_rp_in);
    cudaGetSymbolAddress((void**)&rp_out,  g_rp_out);
    cudaGetSymbolAddress((void**)&cur_in,  g_cur_in);
    cudaGetSymbolAddress((void**)&cur_out, g_cur_out);
    cudaGetSymbolAddress((void**)&edge_in, g_edge_in);
    cudaGetSymbolAddress((void**)&edge_out,g_edge_out);

    const int N = NN, E = EE, TPB = 256;
    const int SMEM_BYTES = (128 * 132 + 2 * 16384) * 4;

    static cudaStream_t s2 = nullptr, s3 = nullptr;
    static cudaEvent_t ev0 = nullptr, evd = nullptr, ev2 = nullptr, ev3 = nullptr;
    if (!s2) {
        cudaStreamCreateWithFlags(&s2, cudaStreamNonBlocking);
        cudaStreamCreateWithFlags(&s3, cudaStreamNonBlocking);
        cudaEventCreateWithFlags(&ev0, cudaEventDisableTiming);
        cudaEventCreateWithFlags(&evd, cudaEventDisableTiming);
        cudaEventCreateWithFlags(&ev2, cudaEventDisableTiming);
        cudaEventCreateWithFlags(&ev3, cudaEventDisableTiming);
        cudaFuncSetAttribute((const void*)tgemm_kernel<256, 256, true>,
                             cudaFuncAttributeMaxDynamicSharedMemorySize, SMEM_BYTES);
        cudaFuncSetAttribute((const void*)tgemm_kernel<192, 128, false>,
                             cudaFuncAttributeMaxDynamicSharedMemorySize, SMEM_BYTES);
    }

    // fork: detect on s2, then in-CSR on s2 and out-CSR on s3, concurrently
    cudaEventRecord(ev0, 0);
    cudaStreamWaitEvent(s2, ev0, 0);
    detect_kernel<<<(N + TPB - 1) / TPB, TPB, 0, s2>>>(ei_in, deg_in, deg_out, N);
    cudaEventRecord(evd, s2);
    cudaStreamWaitEvent(s3, evd, 0);

    count_kernel<<<(E + TPB - 1) / TPB, TPB, 0, s2>>>(ei_in, deg_in, E);
    scan1_kernel<<<1, 1024, 0, s2>>>(deg_in, rp_in, cur_in, N);
    scatter_kernel<<<(E + TPB - 1) / TPB, TPB, 0, s2>>>(ei_in, ew_in, cur_in, edge_in, E);
    cudaEventRecord(ev2, s2);

    count_kernel<<<(E + TPB - 1) / TPB, TPB, 0, s3>>>(ei_out, deg_out, E);
    scan1_kernel<<<1, 1024, 0, s3>>>(deg_out, rp_out, cur_out, N);
    scatter_kernel<<<(E + TPB - 1) / TPB, TPB, 0, s3>>>(ei_out, ew_out, cur_out, edge_out, E);
    cudaEventRecord(ev3, s3);

    // main branch: weight prep + layer-0 GEMM (PE folded into A staging)
    prep_kernel<<<(16384 + 12288 + 448 + TPB - 1) / TPB, TPB>>>(
        Wmi0, Wmo0, Ws0, Wmi1, Wmo1, Ws1, resW,
        bmi0, bsi0, bmo0, bso0, bmi1, bsi1, bmo1, bso1, resb,
        blob0, blob1, bsum);

    const int GBLK = (N + 127) / 128;
    tgemm_kernel<256, 256, true><<<GBLK, 256, SMEM_BYTES>>>(x, pe, blob0, t, nullptr, N);

    // join: gather0 needs both CSRs and t
    cudaStreamWaitEvent(0, ev2, 0);
    cudaStreamWaitEvent(0, ev3, 0);
    gather0_kernel<<<(N * 32 + TPB - 1) / TPB, TPB>>>(
        t, rp_in, edge_in, rp_out, edge_out,
        bsum, cin0, cout0, x, pe, h1, N);

    // layer 1 (residual slice stored fp32)
    tgemm_kernel<192, 128, false><<<GBLK, 256, SMEM_BYTES>>>(h1, pe, blob1, u, res, N);
    gather1_kernel<<<(N * 32 + TPB - 1) / TPB, TPB>>>(
        u, res, rp_in, edge_in, rp_out, edge_out,
        bsum, cin1, cout1, h2, N);

    // decoder + log_softmax + emb
    float* out = (float*)d_out;
    decoder_kernel<<<(N + 15) / 16, 256>>>(h2, decW, decb, out, out + (size_t)N * CLS, N);
}

// round 7
// speedup vs baseline: 1.0939x; 1.0939x over previous
#include <cuda_runtime.h>
#include <cuda_fp16.h>
#include <math.h>

#define NN 50000
#define EE 800000
#define CLS 128

// ---------------- static device scratch ----------------
__device__ __half g_t [NN * 256];
__device__ __half g_u [NN * 128];
__device__ float g_res[NN * 64];
__device__ float g_h1[NN * 128];
__device__ float g_h2[NN * 64];
__device__ float4 g_blob0[16384];   // layer0 weights K=128,N=256, frag order, hi/lo
__device__ float4 g_blob1[12288];   // layer1 weights K=128,N=192 (incl res), frag order
__device__ float4 g_blob2[4096];    // decoder weights K=64,N=128, frag order, hi/lo
__device__ float g_bsum[448];
__device__ int   g_deg_in[NN];
__device__ int   g_deg_out[NN];
__device__ int   g_rp_in[NN + 1];
__device__ int   g_rp_out[NN + 1];
__device__ int   g_cur_in[NN];
__device__ int   g_cur_out[NN];
__device__ int2  g_edge_in[EE];     // packed (src, weight bits)
__device__ int2  g_edge_out[EE];
__device__ int   g_is64;

// ---------------- tf32 helpers ----------------
__device__ __forceinline__ void split_tf32(float a, unsigned& hi, unsigned& lo) {
    asm("cvt.rna.tf32.f32 %0, %1;" : "=r"(hi) : "f"(a));
    float r = a - __uint_as_float(hi);
    asm("cvt.rna.tf32.f32 %0, %1;" : "=r"(lo) : "f"(r));
}

__device__ __forceinline__ void mma_tf32(float4& d,
    unsigned a0, unsigned a1, unsigned a2, unsigned a3,
    unsigned b0, unsigned b1)
{
    asm volatile(
        "mma.sync.aligned.m16n8k8.row.col.f32.tf32.tf32.f32 "
        "{%0,%1,%2,%3},{%4,%5,%6,%7},{%8,%9},{%0,%1,%2,%3};"
        : "+f"(d.x), "+f"(d.y), "+f"(d.z), "+f"(d.w)
        : "r"(a0), "r"(a1), "r"(a2), "r"(a3), "r"(b0), "r"(b1));
}

__device__ __forceinline__ void cp16(void* smem_dst, const void* gsrc, int sz) {
    unsigned du = (unsigned)__cvta_generic_to_shared(smem_dst);
    asm volatile("cp.async.cg.shared.global [%0], [%1], 16, %2;"
                 :: "r"(du), "l"(gsrc), "r"(sz));
}

// ---------------- misc small kernels ----------------
__global__ void detect_kernel(const int* __restrict__ ei, int* __restrict__ da,
                              int* __restrict__ db, int n) {
    if (blockIdx.x == 0 && threadIdx.x == 0) {
        int z = 0;
        for (int i = 1; i < 129; i += 2) z |= ei[i];
        g_is64 = (z == 0) ? 1 : 0;
    }
    int i = blockIdx.x * blockDim.x + threadIdx.x;
    if (i < n) { da[i] = 0; db[i] = 0; }
}

// build frag-ordered, hi/lo-split weight blobs + combined biases
__global__ void prep_kernel(
    const float* __restrict__ Wmi0, const float* __restrict__ Wmo0, const float* __restrict__ Ws0,
    const float* __restrict__ Wmi1, const float* __restrict__ Wmo1, const float* __restrict__ Ws1,
    const float* __restrict__ resW, const float* __restrict__ decW,
    const float* __restrict__ bmi0, const float* __restrict__ bsi0,
    const float* __restrict__ bmo0, const float* __restrict__ bso0,
    const float* __restrict__ bmi1, const float* __restrict__ bsi1,
    const float* __restrict__ bmo1, const float* __restrict__ bso1,
    const float* __restrict__ resb,
    float4* __restrict__ blob0, float4* __restrict__ blob1,
    float4* __restrict__ blob2, float* __restrict__ bsum)
{
    int i = blockIdx.x * blockDim.x + threadIdx.x;
    if (i < 16384) {
        int lane = i & 31; int j = i >> 5;
        int nt = j & 7; j >>= 3;
        int ks = j & 15; j >>= 4;
        int nc = j;
        int n = nc * 64 + nt * 8 + (lane >> 2);
        int ka = ks * 8 + (lane & 3), kb = ka + 4;
        int nn = n & 127;
        float a = Ws0[ka * 128 + nn] + ((n < 128) ? Wmi0[ka * 128 + n] : Wmo0[ka * 128 + n - 128]);
        float b = Ws0[kb * 128 + nn] + ((n < 128) ? Wmi0[kb * 128 + n] : Wmo0[kb * 128 + n - 128]);
        unsigned ha, la, hb, lb;
        split_tf32(a, ha, la); split_tf32(b, hb, lb);
        blob0[i] = make_float4(__uint_as_float(ha), __uint_as_float(hb),
                               __uint_as_float(la), __uint_as_float(lb));
        return;
    }
    int i1 = i - 16384;
    if (i1 < 12288) {
        int lane = i1 & 31; int j = i1 >> 5;
        int nt = j & 7; j >>= 3;
        int ks = j & 15; j >>= 4;
        int nc = j;
        int n = nc * 64 + nt * 8 + (lane >> 2);
        int ka = ks * 8 + (lane & 3), kb = ka + 4;
        float a, b;
        if (n < 128) {
            int nn = n & 63;
            a = Ws1[ka * 64 + nn] + ((n < 64) ? Wmi1[ka * 64 + n] : Wmo1[ka * 64 + n - 64]);
            b = Ws1[kb * 64 + nn] + ((n < 64) ? Wmi1[kb * 64 + n] : Wmo1[kb * 64 + n - 64]);
        } else {
            a = resW[ka * 64 + n - 128];
            b = resW[kb * 64 + n - 128];
        }
        unsigned ha, la, hb, lb;
        split_tf32(a, ha, la); split_tf32(b, hb, lb);
        blob1[i1] = make_float4(__uint_as_float(ha), __uint_as_float(hb),
                                __uint_as_float(la), __uint_as_float(lb));
        return;
    }
    int i2 = i1 - 12288;
    if (i2 < 4096) {
        // decoder: K=64, N=128: index = ((nc*8 + ks)*8 + nt)*32 + lane
        int lane = i2 & 31; int j = i2 >> 5;
        int nt = j & 7; j >>= 3;
        int ks = j & 7; j >>= 3;
        int nc = j;
        int n = nc * 64 + nt * 8 + (lane >> 2);
        int ka = ks * 8 + (lane & 3), kb = ka + 4;
        float a = decW[ka * 128 + n];
        float b = decW[kb * 128 + n];
        unsigned ha, la, hb, lb;
        split_tf32(a, ha, la); split_tf32(b, hb, lb);
        blob2[i2] = make_float4(__uint_as_float(ha), __uint_as_float(hb),
                                __uint_as_float(la), __uint_as_float(lb));
        return;
    }
    int i3 = i2 - 4096;
    if (i3 < 128)       bsum[i3] = bmi0[i3] + bsi0[i3];
    else if (i3 < 256)  bsum[i3] = bmo0[i3 - 128] + bso0[i3 - 128];
    else if (i3 < 320)  bsum[i3] = bmi1[i3 - 256] + bsi1[i3 - 256];
    else if (i3 < 384)  bsum[i3] = bmo1[i3 - 320] + bso1[i3 - 320];
    else if (i3 < 448)  bsum[i3] = resb[i3 - 384];
}

// ---------------- CSR build (fused dual, packed int2 payload) ----------------
__global__ void count_dual_kernel(const int* __restrict__ ei_a, const int* __restrict__ ei_b,
                                  int* __restrict__ deg_a, int* __restrict__ deg_b, int E)
{
    int e = blockIdx.x * blockDim.x + threadIdx.x;
    int which = (e >= E);
    int idx = which ? e - E : e;
    if (idx >= E) return;
    const int* ei = which ? ei_b : ei_a;
    int* deg = which ? deg_b : deg_a;
    int tgt;
    if (g_is64) tgt = (int)((const long long*)ei)[E + idx];
    else        tgt = ei[E + idx];
    atomicAdd(deg + tgt, 1);
}

__global__ __launch_bounds__(1024) void scan_kernel(
    const int* __restrict__ deg_in, const int* __restrict__ deg_out,
    int* __restrict__ rp_in, int* __restrict__ rp_out,
    int* __restrict__ cur_in, int* __restrict__ cur_out, int n)
{
    const int* deg = blockIdx.x ? deg_out : deg_in;
    int* rp  = blockIdx.x ? rp_out  : rp_in;
    int* cur = blockIdx.x ? cur_out : cur_in;
    __shared__ int wsum[32];
    int tid = threadIdx.x, lane = tid & 31, wid = tid >> 5;
    int carry = 0;
    for (int base = 0; base < n; base += 1024) {
        int i = base + tid;
        int x = (i < n) ? deg[i] : 0;
        int v = x;
#pragma unroll
        for (int off = 1; off < 32; off <<= 1) {
            int t = __shfl_up_sync(0xffffffffu, v, off);
            if (lane >= off) v += t;
        }
        if (lane == 31) wsum[wid] = v;
        __syncthreads();
        if (wid == 0) {
            int w = wsum[lane];
#pragma unroll
            for (int off = 1; off < 32; off <<= 1) {
                int t = __shfl_up_sync(0xffffffffu, w, off);
                if (lane >= off) w += t;
            }
            wsum[lane] = w;
        }
        __syncthreads();
        int woff = wid ? wsum[wid - 1] : 0;
        int total = wsum[31];
        if (i < n) {
            int excl = carry + woff + v - x;
            rp[i] = excl;
            cur[i] = excl;
        }
        carry += total;
        __syncthreads();
    }
    if (tid == 0) rp[n] = carry;
}

__global__ void scatter_dual_kernel(
    const int* __restrict__ ei_a, const float* __restrict__ ew_a,
    const int* __restrict__ ei_b, const float* __restrict__ ew_b,
    int* __restrict__ cur_a, int* __restrict__ cur_b,
    int2* __restrict__ edge_a, int2* __restrict__ edge_b, int E)
{
    int e = blockIdx.x * blockDim.x + threadIdx.x;
    int which = (e >= E);
    int idx = which ? e - E : e;
    if (idx >= E) return;
    const int* ei   = which ? ei_b : ei_a;
    const float* ew = which ? ew_b : ew_a;
    int* cur   = which ? cur_b : cur_a;
    int2* edge = which ? edge_b : edge_a;
    int src, tgt;
    if (g_is64) {
        const long long* p = (const long long*)ei;
        src = (int)p[idx]; tgt = (int)p[E + idx];
    } else {
        src = ei[idx]; tgt = ei[E + idx];
    }
    int pos = atomicAdd(cur + tgt, 1);
    edge[pos] = make_int2(src, __float_as_int(ew[idx]));
}

// ---------------- tensor-core GEMM: (H (+pe)) @ W -------------------------
// fp16 output for the first HC cols (edge-gathered), fp32 for cols >= HC (residual).
template<int N, int HC, bool ADD_PE>
__global__ __launch_bounds__(256) void tgemm_kernel(
    const float* __restrict__ H, const float* __restrict__ pe,
    const float4* __restrict__ Wblob, __half* __restrict__ outH,
    float* __restrict__ outF, int nrows)
{
    constexpr int K = 128;
    constexpr int CHUNKS = N / 64;
    constexpr int AST = K + 4;
    extern __shared__ float smem[];
    float* shA  = smem;
    float* shB0 = smem + 128 * AST;
    float* shB1 = shB0 + 16384;

    const int tid  = threadIdx.x;
    const int lane = tid & 31;
    const int wm   = (tid >> 5) * 16;
    const int g    = lane >> 2;
    const int row0 = blockIdx.x * 128;

#pragma unroll
    for (int i = 0; i < 16; i++) {
        int lin = tid + 256 * i;
        int r = lin >> 5, c4 = (lin & 31) << 2;
        int sz = (row0 + r < nrows) ? 16 : 0;
        cp16(shA + r * AST + c4, H + (size_t)(row0 + r) * K + c4, sz);
    }
#pragma unroll
    for (int i = 0; i < 16; i++) {
        int lin = tid + 256 * i;
        cp16(shB0 + lin * 4, Wblob + lin, 16);
    }
    asm volatile("cp.async.commit_group;");
    asm volatile("cp.async.wait_group 0;");
    __syncthreads();

    if (ADD_PE) {
        int c4 = (tid & 31) << 2;
        float4 pv = *reinterpret_cast<const float4*>(pe + c4);
#pragma unroll
        for (int i = 0; i < 16; i++) {
            int r = (tid + 256 * i) >> 5;
            float4 v = *reinterpret_cast<float4*>(shA + r * AST + c4);
            v.x += pv.x; v.y += pv.y; v.z += pv.z; v.w += pv.w;
            *reinterpret_cast<float4*>(shA + r * AST + c4) = v;
        }
        __syncthreads();
    }

    for (int c = 0; c < CHUNKS; c++) {
        if (c + 1 < CHUNKS) {
            float* nb = ((c + 1) & 1) ? shB1 : shB0;
            const float4* src = Wblob + (size_t)(c + 1) * 4096;
#pragma unroll
            for (int i = 0; i < 16; i++) {
                int lin = tid + 256 * i;
                cp16(nb + lin * 4, src + lin, 16);
            }
            asm volatile("cp.async.commit_group;");
        }

        const float* shB = (c & 1) ? shB1 : shB0;
        float4 acc[8];
#pragma unroll
        for (int nt = 0; nt < 8; nt++) acc[nt] = make_float4(0.f, 0.f, 0.f, 0.f);

#pragma unroll 2
        for (int ks = 0; ks < 16; ks++) {
            int ka = ks * 8 + (lane & 3);
            const float* ap = shA + (wm + g) * AST + ka;
            float a0 = ap[0], a2 = ap[4];
            float a1 = ap[8 * AST], a3 = ap[8 * AST + 4];
            unsigned h0, l0, h1, l1, h2, l2, h3, l3;
            split_tf32(a0, h0, l0); split_tf32(a1, h1, l1);
            split_tf32(a2, h2, l2); split_tf32(a3, h3, l3);
            const uint4* bp = reinterpret_cast<const uint4*>(shB) + ks * 256 + lane;
#pragma unroll
            for (int nt = 0; nt < 8; nt++) {
                uint4 b = bp[nt * 32];
                mma_tf32(acc[nt], h0, h1, h2, h3, b.x, b.y);
                mma_tf32(acc[nt], h0, h1, h2, h3, b.z, b.w);
                mma_tf32(acc[nt], l0, l1, l2, l3, b.x, b.y);
            }
        }

        int r1 = row0 + wm + g, r2 = r1 + 8;
        int colb = c * 64 + 2 * (lane & 3);
        if (colb < HC) {
#pragma unroll
            for (int nt = 0; nt < 8; nt++) {
                int col = colb + nt * 8;
                if (r1 < nrows)
                    *reinterpret_cast<__half2*>(outH + (size_t)r1 * HC + col) =
                        __floats2half2_rn(acc[nt].x, acc[nt].y);
                if (r2 < nrows)
                    *reinterpret_cast<__half2*>(outH + (size_t)r2 * HC + col) =
                        __floats2half2_rn(acc[nt].z, acc[nt].w);
            }
        } else {
#pragma unroll
            for (int nt = 0; nt < 8; nt++) {
                int col = colb - HC + nt * 8;
                if (r1 < nrows)
                    *reinterpret_cast<float2*>(outF + (size_t)r1 * (N - HC) + col) =
                        make_float2(acc[nt].x, acc[nt].y);
                if (r2 < nrows)
                    *reinterpret_cast<float2*>(outF + (size_t)r2 * (N - HC) + col) =
                        make_float2(acc[nt].z, acc[nt].w);
            }
        }

        asm volatile("cp.async.wait_group 0;");
        __syncthreads();
    }
}

// ---------------- layer-0 gather+combine: warp per node (fp16 t) -----------
__global__ __launch_bounds__(256) void gather0_kernel(
    const __half* __restrict__ t,
    const int* __restrict__ rpi, const int2* __restrict__ egi,
    const int* __restrict__ rpo, const int2* __restrict__ ego,
    const float* __restrict__ bsum,
    const float* __restrict__ cin, const float* __restrict__ cout,
    const float* __restrict__ x, const float* __restrict__ pe,
    float* __restrict__ h1, int n)
{
    int node = (blockIdx.x * 256 + threadIdx.x) >> 5;
    int lane = threadIdx.x & 31;
    if (node >= n) return;

    float4 ic = make_float4(0.f, 0.f, 0.f, 0.f);
    float4 oc = make_float4(0.f, 0.f, 0.f, 0.f);

    int s = rpi[node], e = rpi[node + 1];
#pragma unroll 4
    for (int k = s; k < e; k++) {
        int2 ed = __ldg(egi + k);
        float w = __int_as_float(ed.y);
        float2 raw = *reinterpret_cast<const float2*>(t + (size_t)ed.x * 256 + lane * 4);
        float2 a = __half22float2(*reinterpret_cast<const __half2*>(&raw.x));
        float2 b = __half22float2(*reinterpret_cast<const __half2*>(&raw.y));
        ic.x += w * a.x; ic.y += w * a.y; ic.z += w * b.x; ic.w += w * b.y;
    }
    s = rpo[node]; e = rpo[node + 1];
#pragma unroll 4
    for (int k = s; k < e; k++) {
        int2 ed = __ldg(ego + k);
        float w = __int_as_float(ed.y);
        float2 raw = *reinterpret_cast<const float2*>(t + (size_t)ed.x * 256 + 128 + lane * 4);
        float2 a = __half22float2(*reinterpret_cast<const __half2*>(&raw.x));
        float2 b = __half22float2(*reinterpret_cast<const __half2*>(&raw.y));
        oc.x += w * a.x; oc.y += w * a.y; oc.z += w * b.x; oc.w += w * b.y;
    }

    float ci = __ldg(cin + node), co = __ldg(cout + node);
    float4 bi = *reinterpret_cast<const float4*>(bsum + lane * 4);
    float4 bo = *reinterpret_cast<const float4*>(bsum + 128 + lane * 4);
    float4 r  = *reinterpret_cast<const float4*>(x + (size_t)node * 128 + lane * 4);
    float4 pv = *reinterpret_cast<const float4*>(pe + lane * 4);
    r.x += pv.x; r.y += pv.y; r.z += pv.z; r.w += pv.w;
    float4 o;
    o.x = tanhf(ci * (ic.x + bi.x) + co * (oc.x + bo.x) + r.x);
    o.y = tanhf(ci * (ic.y + bi.y) + co * (oc.y + bo.y) + r.y);
    o.z = tanhf(ci * (ic.z + bi.z) + co * (oc.z + bo.z) + r.z);
    o.w = tanhf(ci * (ic.w + bi.w) + co * (oc.w + bo.w) + r.w);
    *reinterpret_cast<float4*>(h1 + (size_t)node * 128 + lane * 4) = o;
}

// ---------------- layer-1 gather+combine (fp16 u stride 128, fp32 res) -----
__global__ __launch_bounds__(256) void gather1_kernel(
    const __half* __restrict__ u, const float* __restrict__ res,
    const int* __restrict__ rpi, const int2* __restrict__ egi,
    const int* __restrict__ rpo, const int2* __restrict__ ego,
    const float* __restrict__ bsum,
    const float* __restrict__ cin, const float* __restrict__ cout,
    float* __restrict__ h2, int n)
{
    int node = (blockIdx.x * 256 + threadIdx.x) >> 5;
    int lane = threadIdx.x & 31;
    if (node >= n) return;

    float2 ic = make_float2(0.f, 0.f);
    float2 oc = make_float2(0.f, 0.f);

    int s = rpi[node], e = rpi[node + 1];
#pragma unroll 4
    for (int k = s; k < e; k++) {
        int2 ed = __ldg(egi + k);
        float w = __int_as_float(ed.y);
        float2 v = __half22float2(*reinterpret_cast<const __half2*>(u + (size_t)ed.x * 128 + lane * 2));
        ic.x += w * v.x; ic.y += w * v.y;
    }
    s = rpo[node]; e = rpo[node + 1];
#pragma unroll 4
    for (int k = s; k < e; k++) {
        int2 ed = __ldg(ego + k);
        float w = __int_as_float(ed.y);
        float2 v = __half22float2(*reinterpret_cast<const __half2*>(u + (size_t)ed.x * 128 + 64 + lane * 2));
        oc.x += w * v.x; oc.y += w * v.y;
    }

    float ci = __ldg(cin + node), co = __ldg(cout + node);
    float2 bi = *reinterpret_cast<const float2*>(bsum + 256 + lane * 2);
    float2 bo = *reinterpret_cast<const float2*>(bsum + 320 + lane * 2);
    float2 rb = *reinterpret_cast<const float2*>(bsum + 384 + lane * 2);
    float2 r  = *reinterpret_cast<const float2*>(res + (size_t)node * 64 + lane * 2);
    float2 o;
    o.x = tanhf(ci * (ic.x + bi.x) + co * (oc.x + bo.x) + r.x + rb.x);
    o.y = tanhf(ci * (ic.y + bi.y) + co * (oc.y + bo.y) + r.y + rb.y);
    *reinterpret_cast<float2*>(h2 + (size_t)node * 64 + lane * 2) = o;
}

// ---------------- decoder: tensor GEMM + in-register log_softmax + emb -----
// K=64 (h2), N=128 (classes). 128 rows per CTA, 8 warps (warp = 16 rows).
__global__ __launch_bounds__(256) void dec_kernel(
    const float* __restrict__ h2, const float4* __restrict__ Wblob,
    const float* __restrict__ bias, float* __restrict__ logp,
    float* __restrict__ emb, int nrows)
{
    constexpr int AST = 68;
    extern __shared__ float smem[];
    float* shA = smem;                 // 128 * 68 floats
    float* shB = smem + 128 * AST;     // 16384 floats (4096 float4)

    const int tid  = threadIdx.x;
    const int lane = tid & 31;
    const int wm   = (tid >> 5) * 16;
    const int g    = lane >> 2;
    const int q    = lane & 3;
    const int row0 = blockIdx.x * 128;

    // stage A (h2): 128 rows x 64 floats = 2048 float4
#pragma unroll
    for (int i = 0; i < 8; i++) {
        int lin = tid + 256 * i;
        int r = lin >> 4, c4 = (lin & 15) << 2;
        int sz = (row0 + r < nrows) ? 16 : 0;
        cp16(shA + r * AST + c4, h2 + (size_t)(row0 + r) * 64 + c4, sz);
    }
    // stage B: 4096 float4
#pragma unroll
    for (int i = 0; i < 16; i++) {
        int lin = tid + 256 * i;
        cp16(shB + lin * 4, Wblob + lin, 16);
    }
    asm volatile("cp.async.commit_group;");
    asm volatile("cp.async.wait_group 0;");
    __syncthreads();

    float4 acc[2][8];
#pragma unroll
    for (int c = 0; c < 2; c++)
#pragma unroll
        for (int nt = 0; nt < 8; nt++) acc[c][nt] = make_float4(0.f, 0.f, 0.f, 0.f);

#pragma unroll
    for (int c = 0; c < 2; c++) {
#pragma unroll
        for (int ks = 0; ks < 8; ks++) {
            int ka = ks * 8 + q;
            const float* ap = shA + (wm + g) * AST + ka;
            float a0 = ap[0], a2 = ap[4];
            float a1 = ap[8 * AST], a3 = ap[8 * AST + 4];
            unsigned h0, l0, h1, l1, h2r, l2, h3, l3;
            split_tf32(a0, h0, l0); split_tf32(a1, h1, l1);
            split_tf32(a2, h2r, l2); split_tf32(a3, h3, l3);
            const uint4* bp = reinterpret_cast<const uint4*>(shB) + c * 2048 + ks * 256 + lane;
#pragma unroll
            for (int nt = 0; nt < 8; nt++) {
                uint4 b = bp[nt * 32];
                mma_tf32(acc[c][nt], h0, h1, h2r, h3, b.x, b.y);
                mma_tf32(acc[c][nt], h0, h1, h2r, h3, b.z, b.w);
                mma_tf32(acc[c][nt], l0, l1, l2, l3, b.x, b.y);
            }
        }
    }

    int r1 = row0 + wm + g, r2 = r1 + 8;

    // bias + row max (rows' 128 logits live across quad lanes)
    float m1 = -1e30f, m2 = -1e30f;
#pragma unroll
    for (int c = 0; c < 2; c++)
#pragma unroll
        for (int nt = 0; nt < 8; nt++) {
            float2 bb = *reinterpret_cast<const float2*>(bias + c * 64 + nt * 8 + 2 * q);
            acc[c][nt].x += bb.x; acc[c][nt].y += bb.y;
            acc[c][nt].z += bb.x; acc[c][nt].w += bb.y;
            m1 = fmaxf(m1, fmaxf(acc[c][nt].x, acc[c][nt].y));
            m2 = fmaxf(m2, fmaxf(acc[c][nt].z, acc[c][nt].w));
        }
    m1 = fmaxf(m1, __shfl_xor_sync(0xffffffffu, m1, 1));
    m1 = fmaxf(m1, __shfl_xor_sync(0xffffffffu, m1, 2));
    m2 = fmaxf(m2, __shfl_xor_sync(0xffffffffu, m2, 1));
    m2 = fmaxf(m2, __shfl_xor_sync(0xffffffffu, m2, 2));

    float s1 = 0.f, s2 = 0.f;
#pragma unroll
    for (int c = 0; c < 2; c++)
#pragma unroll
        for (int nt = 0; nt < 8; nt++) {
            s1 += expf(acc[c][nt].x - m1) + expf(acc[c][nt].y - m1);
            s2 += expf(acc[c][nt].z - m2) + expf(acc[c][nt].w - m2);
        }
    s1 += __shfl_xor_sync(0xffffffffu, s1, 1);
    s1 += __shfl_xor_sync(0xffffffffu, s1, 2);
    s2 += __shfl_xor_sync(0xffffffffu, s2, 1);
    s2 += __shfl_xor_sync(0xffffffffu, s2, 2);
    float lse1 = m1 + logf(s1), lse2 = m2 + logf(s2);

#pragma unroll
    for (int c = 0; c < 2; c++)
#pragma unroll
        for (int nt = 0; nt < 8; nt++) {
            int col = c * 64 + nt * 8 + 2 * q;
            if (r1 < nrows)
                *reinterpret_cast<float2*>(logp + (size_t)r1 * CLS + col) =
                    make_float2(acc[c][nt].x - lse1, acc[c][nt].y - lse1);
            if (r2 < nrows)
                *reinterpret_cast<float2*>(logp + (size_t)r2 * CLS + col) =
                    make_float2(acc[c][nt].z - lse2, acc[c][nt].w - lse2);
        }

    // emb: L2-normalize the h2 rows straight from smem (quad q covers 16 dims)
    const float* ar1 = shA + (wm + g) * AST;
    const float* ar2 = ar1 + 8 * AST;
    float4 v1[4], v2[4];
    float sq1 = 0.f, sq2 = 0.f;
#pragma unroll
    for (int j = 0; j < 4; j++) {
        v1[j] = *reinterpret_cast<const float4*>(ar1 + q * 16 + j * 4);
        v2[j] = *reinterpret_cast<const float4*>(ar2 + q * 16 + j * 4);
        sq1 += v1[j].x * v1[j].x + v1[j].y * v1[j].y + v1[j].z * v1[j].z + v1[j].w * v1[j].w;
        sq2 += v2[j].x * v2[j].x + v2[j].y * v2[j].y + v2[j].z * v2[j].z + v2[j].w * v2[j].w;
    }
    sq1 += __shfl_xor_sync(0xffffffffu, sq1, 1);
    sq1 += __shfl_xor_sync(0xffffffffu, sq1, 2);
    sq2 += __shfl_xor_sync(0xffffffffu, sq2, 1);
    sq2 += __shfl_xor_sync(0xffffffffu, sq2, 2);
    float inv1 = 1.f / (sqrtf(sq1) + 1e-12f);
    float inv2 = 1.f / (sqrtf(sq2) + 1e-12f);
#pragma unroll
    for (int j = 0; j < 4; j++) {
        if (r1 < nrows)
            *reinterpret_cast<float4*>(emb + (size_t)r1 * 64 + q * 16 + j * 4) =
                make_float4(v1[j].x * inv1, v1[j].y * inv1, v1[j].z * inv1, v1[j].w * inv1);
        if (r2 < nrows)
            *reinterpret_cast<float4*>(emb + (size_t)r2 * 64 + q * 16 + j * 4) =
                make_float4(v2[j].x * inv2, v2[j].y * inv2, v2[j].z * inv2, v2[j].w * inv2);
    }
}

// ---------------- host ----------------
extern "C" void kernel_launch(void* const* d_in, const int* in_sizes, int n_in,
                              void* d_out, int out_size)
{
    const float* x      = (const float*)d_in[0];
    const int*   ei_in  = (const int*)d_in[1];
    const float* ew_in  = (const float*)d_in[2];
    const int*   ei_out = (const int*)d_in[3];
    const float* ew_out = (const float*)d_in[4];
    const float* pe     = (const float*)d_in[5];

    const float* Wmi0 = (const float*)d_in[6];
    const float* Wmo0 = (const float*)d_in[7];
    const float* Ws0  = (const float*)d_in[8];
    const float* bmi0 = (const float*)d_in[9];
    const float* bmo0 = (const float*)d_in[10];
    const float* bsi0 = (const float*)d_in[11];
    const float* bso0 = (const float*)d_in[12];
    const float* cin0 = (const float*)d_in[13];
    const float* cout0= (const float*)d_in[14];

    const float* Wmi1 = (const float*)d_in[15];
    const float* Wmo1 = (const float*)d_in[16];
    const float* Ws1  = (const float*)d_in[17];
    const float* bmi1 = (const float*)d_in[18];
    const float* bmo1 = (const float*)d_in[19];
    const float* bsi1 = (const float*)d_in[20];
    const float* bso1 = (const float*)d_in[21];
    const float* cin1 = (const float*)d_in[22];
    const float* cout1= (const float*)d_in[23];

    const float* resW = (const float*)d_in[24];
    const float* resb = (const float*)d_in[25];
    const float* decW = (const float*)d_in[26];
    const float* decb = (const float*)d_in[27];

    __half *t, *u;
    float *res, *h1, *h2, *bsum;
    float4 *blob0, *blob1, *blob2;
    int *deg_in, *deg_out, *rp_in, *rp_out, *cur_in, *cur_out;
    int2 *edge_in, *edge_out;
    cudaGetSymbolAddress((void**)&t,   g_t);
    cudaGetSymbolAddress((void**)&u,   g_u);
    cudaGetSymbolAddress((void**)&res, g_res);
    cudaGetSymbolAddress((void**)&h1,  g_h1);
    cudaGetSymbolAddress((void**)&h2,  g_h2);
    cudaGetSymbolAddress((void**)&blob0, g_blob0);
    cudaGetSymbolAddress((void**)&blob1, g_blob1);
    cudaGetSymbolAddress((void**)&blob2, g_blob2);
    cudaGetSymbolAddress((void**)&bsum,g_bsum);
    cudaGetSymbolAddress((void**)&deg_in,  g_deg_in);
    cudaGetSymbolAddress((void**)&deg_out, g_deg_out);
    cudaGetSymbolAddress((void**)&rp_in,   g_rp_in);
    cudaGetSymbolAddress((void**)&rp_out,  g_rp_out);
    cudaGetSymbolAddress((void**)&cur_in,  g_cur_in);
    cudaGetSymbolAddress((void**)&cur_out, g_cur_out);
    cudaGetSymbolAddress((void**)&edge_in, g_edge_in);
    cudaGetSymbolAddress((void**)&edge_out,g_edge_out);

    const int N = NN, E = EE, TPB = 256;
    const int SMEM_BYTES = (128 * 132 + 2 * 16384) * 4;
    const int SMEM_DEC   = (128 * 68 + 16384) * 4;

    static cudaStream_t s2 = nullptr;
    static cudaEvent_t ev0 = nullptr, ev2 = nullptr;
    if (!s2) {
        cudaStreamCreateWithFlags(&s2, cudaStreamNonBlocking);
        cudaEventCreateWithFlags(&ev0, cudaEventDisableTiming);
        cudaEventCreateWithFlags(&ev2, cudaEventDisableTiming);
        cudaFuncSetAttribute((const void*)tgemm_kernel<256, 256, true>,
                             cudaFuncAttributeMaxDynamicSharedMemorySize, SMEM_BYTES);
        cudaFuncSetAttribute((const void*)tgemm_kernel<192, 128, false>,
                             cudaFuncAttributeMaxDynamicSharedMemorySize, SMEM_BYTES);
        cudaFuncSetAttribute((const void*)dec_kernel,
                             cudaFuncAttributeMaxDynamicSharedMemorySize, SMEM_DEC);
    }

    // fork CSR branch onto s2
    cudaEventRecord(ev0, 0);
    cudaStreamWaitEvent(s2, ev0, 0);
    detect_kernel<<<(N + TPB - 1) / TPB, TPB, 0, s2>>>(ei_in, deg_in, deg_out, N);
    count_dual_kernel<<<(2 * E + TPB - 1) / TPB, TPB, 0, s2>>>(ei_in, ei_out, deg_in, deg_out, E);
    scan_kernel<<<2, 1024, 0, s2>>>(deg_in, deg_out, rp_in, rp_out, cur_in, cur_out, N);
    scatter_dual_kernel<<<(2 * E + TPB - 1) / TPB, TPB, 0, s2>>>(
        ei_in, ew_in, ei_out, ew_out, cur_in, cur_out, edge_in, edge_out, E);
    cudaEventRecord(ev2, s2);

    // main branch: weight prep + layer-0 GEMM (PE folded into A staging)
    prep_kernel<<<(16384 + 12288 + 4096 + 448 + TPB - 1) / TPB, TPB>>>(
        Wmi0, Wmo0, Ws0, Wmi1, Wmo1, Ws1, resW, decW,
        bmi0, bsi0, bmo0, bso0, bmi1, bsi1, bmo1, bso1, resb,
        blob0, blob1, blob2, bsum);

    const int GBLK = (N + 127) / 128;
    tgemm_kernel<256, 256, true><<<GBLK, 256, SMEM_BYTES>>>(x, pe, blob0, t, nullptr, N);

    // join: gather0 needs CSR and t
    cudaStreamWaitEvent(0, ev2, 0);
    gather0_kernel<<<(N * 32 + TPB - 1) / TPB, TPB>>>(
        t, rp_in, edge_in, rp_out, edge_out,
        bsum, cin0, cout0, x, pe, h1, N);

    // layer 1 (residual slice stored fp32)
    tgemm_kernel<192, 128, false><<<GBLK, 256, SMEM_BYTES>>>(h1, pe, blob1, u, res, N);
    gather1_kernel<<<(N * 32 + TPB - 1) / TPB, TPB>>>(
        u, res, rp_in, edge_in, rp_out, edge_out,
        bsum, cin1, cout1, h2, N);

    // fused decoder: tensor GEMM + log_softmax + L2-normalized emb
    float* out = (float*)d_out;
    dec_kernel<<<GBLK, 256, SMEM_DEC>>>(h2, blob2, decb, out, out + (size_t)N * CLS, N);
}

// round 8
// speedup vs baseline: 1.1870x; 1.0851x over previous
#include <cuda_runtime.h>
#include <cuda_fp16.h>
#include <math.h>

#define NN 50000
#define EE 800000
#define CLS 128
#define CAP 64

// ---------------- static device scratch ----------------
__device__ __half g_t [NN * 256];
__device__ __half g_u [NN * 128];
__device__ float g_res[NN * 64];
__device__ float g_h1[NN * 128];
__device__ float g_h2[NN * 64];
__device__ float4 g_blob0[16384];   // layer0 weights K=128,N=256, frag order, hi/lo
__device__ float4 g_blob1[12288];   // layer1 weights K=128,N=192 (incl res), frag order
__device__ float4 g_blob2[4096];    // decoder weights K=64,N=128, frag order, hi/lo
__device__ float g_bsum[448];
__device__ int   g_deg_in[NN];
__device__ int   g_deg_out[NN];
__device__ int2  g_edge_in [NN * CAP];  // per-node bucket: (src, weight bits)
__device__ int2  g_edge_out[NN * CAP];
__device__ int   g_is64;

// ---------------- tf32 helpers ----------------
__device__ __forceinline__ void split_tf32(float a, unsigned& hi, unsigned& lo) {
    asm("cvt.rna.tf32.f32 %0, %1;" : "=r"(hi) : "f"(a));
    float r = a - __uint_as_float(hi);
    asm("cvt.rna.tf32.f32 %0, %1;" : "=r"(lo) : "f"(r));
}

__device__ __forceinline__ void mma_tf32(float4& d,
    unsigned a0, unsigned a1, unsigned a2, unsigned a3,
    unsigned b0, unsigned b1)
{
    asm volatile(
        "mma.sync.aligned.m16n8k8.row.col.f32.tf32.tf32.f32 "
        "{%0,%1,%2,%3},{%4,%5,%6,%7},{%8,%9},{%0,%1,%2,%3};"
        : "+f"(d.x), "+f"(d.y), "+f"(d.z), "+f"(d.w)
        : "r"(a0), "r"(a1), "r"(a2), "r"(a3), "r"(b0), "r"(b1));
}

__device__ __forceinline__ void cp16(void* smem_dst, const void* gsrc, int sz) {
    unsigned du = (unsigned)__cvta_generic_to_shared(smem_dst);
    asm volatile("cp.async.cg.shared.global [%0], [%1], 16, %2;"
                 :: "r"(du), "l"(gsrc), "r"(sz));
}

// ---------------- misc small kernels ----------------
__global__ void detect_kernel(const int* __restrict__ ei, int* __restrict__ da,
                              int* __restrict__ db, int n) {
    if (blockIdx.x == 0 && threadIdx.x == 0) {
        int z = 0;
        for (int i = 1; i < 129; i += 2) z |= ei[i];
        g_is64 = (z == 0) ? 1 : 0;
    }
    int i = blockIdx.x * blockDim.x + threadIdx.x;
    if (i < n) { da[i] = 0; db[i] = 0; }
}

// build frag-ordered, hi/lo-split weight blobs + combined biases
__global__ void prep_kernel(
    const float* __restrict__ Wmi0, const float* __restrict__ Wmo0, const float* __restrict__ Ws0,
    const float* __restrict__ Wmi1, const float* __restrict__ Wmo1, const float* __restrict__ Ws1,
    const float* __restrict__ resW, const float* __restrict__ decW,
    const float* __restrict__ bmi0, const float* __restrict__ bsi0,
    const float* __restrict__ bmo0, const float* __restrict__ bso0,
    const float* __restrict__ bmi1, const float* __restrict__ bsi1,
    const float* __restrict__ bmo1, const float* __restrict__ bso1,
    const float* __restrict__ resb,
    float4* __restrict__ blob0, float4* __restrict__ blob1,
    float4* __restrict__ blob2, float* __restrict__ bsum)
{
    int i = blockIdx.x * blockDim.x + threadIdx.x;
    if (i < 16384) {
        int lane = i & 31; int j = i >> 5;
        int nt = j & 7; j >>= 3;
        int ks = j & 15; j >>= 4;
        int nc = j;
        int n = nc * 64 + nt * 8 + (lane >> 2);
        int ka = ks * 8 + (lane & 3), kb = ka + 4;
        int nn = n & 127;
        float a = Ws0[ka * 128 + nn] + ((n < 128) ? Wmi0[ka * 128 + n] : Wmo0[ka * 128 + n - 128]);
        float b = Ws0[kb * 128 + nn] + ((n < 128) ? Wmi0[kb * 128 + n] : Wmo0[kb * 128 + n - 128]);
        unsigned ha, la, hb, lb;
        split_tf32(a, ha, la); split_tf32(b, hb, lb);
        blob0[i] = make_float4(__uint_as_float(ha), __uint_as_float(hb),
                               __uint_as_float(la), __uint_as_float(lb));
        return;
    }
    int i1 = i - 16384;
    if (i1 < 12288) {
        int lane = i1 & 31; int j = i1 >> 5;
        int nt = j & 7; j >>= 3;
        int ks = j & 15; j >>= 4;
        int nc = j;
        int n = nc * 64 + nt * 8 + (lane >> 2);
        int ka = ks * 8 + (lane & 3), kb = ka + 4;
        float a, b;
        if (n < 128) {
            int nn = n & 63;
            a = Ws1[ka * 64 + nn] + ((n < 64) ? Wmi1[ka * 64 + n] : Wmo1[ka * 64 + n - 64]);
            b = Ws1[kb * 64 + nn] + ((n < 64) ? Wmi1[kb * 64 + n] : Wmo1[kb * 64 + n - 64]);
        } else {
            a = resW[ka * 64 + n - 128];
            b = resW[kb * 64 + n - 128];
        }
        unsigned ha, la, hb, lb;
        split_tf32(a, ha, la); split_tf32(b, hb, lb);
        blob1[i1] = make_float4(__uint_as_float(ha), __uint_as_float(hb),
                                __uint_as_float(la), __uint_as_float(lb));
        return;
    }
    int i2 = i1 - 12288;
    if (i2 < 4096) {
        int lane = i2 & 31; int j = i2 >> 5;
        int nt = j & 7; j >>= 3;
        int ks = j & 7; j >>= 3;
        int nc = j;
        int n = nc * 64 + nt * 8 + (lane >> 2);
        int ka = ks * 8 + (lane & 3), kb = ka + 4;
        float a = decW[ka * 128 + n];
        float b = decW[kb * 128 + n];
        unsigned ha, la, hb, lb;
        split_tf32(a, ha, la); split_tf32(b, hb, lb);
        blob2[i2] = make_float4(__uint_as_float(ha), __uint_as_float(hb),
                                __uint_as_float(la), __uint_as_float(lb));
        return;
    }
    int i3 = i2 - 4096;
    if (i3 < 128)       bsum[i3] = bmi0[i3] + bsi0[i3];
    else if (i3 < 256)  bsum[i3] = bmo0[i3 - 128] + bso0[i3 - 128];
    else if (i3 < 320)  bsum[i3] = bmi1[i3 - 256] + bsi1[i3 - 256];
    else if (i3 < 384)  bsum[i3] = bmo1[i3 - 320] + bso1[i3 - 320];
    else if (i3 < 448)  bsum[i3] = resb[i3 - 384];
}

// ---------------- direct bucket scatter (no count/scan) --------------------
__global__ void scatter_dual_kernel(
    const int* __restrict__ ei_a, const float* __restrict__ ew_a,
    const int* __restrict__ ei_b, const float* __restrict__ ew_b,
    int* __restrict__ deg_a, int* __restrict__ deg_b,
    int2* __restrict__ edge_a, int2* __restrict__ edge_b, int E)
{
    int e = blockIdx.x * blockDim.x + threadIdx.x;
    int which = (e >= E);
    int idx = which ? e - E : e;
    if (idx >= E) return;
    const int* ei   = which ? ei_b : ei_a;
    const float* ew = which ? ew_b : ew_a;
    int* deg   = which ? deg_b : deg_a;
    int2* edge = which ? edge_b : edge_a;
    int src, tgt;
    if (g_is64) {
        const long long* p = (const long long*)ei;
        src = (int)p[idx]; tgt = (int)p[E + idx];
    } else {
        src = ei[idx]; tgt = ei[E + idx];
    }
    int pos = atomicAdd(deg + tgt, 1);
    if (pos < CAP)
        edge[tgt * CAP + pos] = make_int2(src, __float_as_int(ew[idx]));
}

// ---------------- tensor-core GEMM: (H (+pe)) @ W -------------------------
// fp16 output for the first HC cols (edge-gathered), fp32 for cols >= HC (residual).
template<int N, int HC, bool ADD_PE>
__global__ __launch_bounds__(256) void tgemm_kernel(
    const float* __restrict__ H, const float* __restrict__ pe,
    const float4* __restrict__ Wblob, __half* __restrict__ outH,
    float* __restrict__ outF, int nrows)
{
    constexpr int K = 128;
    constexpr int CHUNKS = N / 64;
    constexpr int AST = K + 4;
    extern __shared__ float smem[];
    float* shA  = smem;
    float* shB0 = smem + 128 * AST;
    float* shB1 = shB0 + 16384;

    const int tid  = threadIdx.x;
    const int lane = tid & 31;
    const int wm   = (tid >> 5) * 16;
    const int g    = lane >> 2;
    const int row0 = blockIdx.x * 128;

#pragma unroll
    for (int i = 0; i < 16; i++) {
        int lin = tid + 256 * i;
        int r = lin >> 5, c4 = (lin & 31) << 2;
        int sz = (row0 + r < nrows) ? 16 : 0;
        cp16(shA + r * AST + c4, H + (size_t)(row0 + r) * K + c4, sz);
    }
#pragma unroll
    for (int i = 0; i < 16; i++) {
        int lin = tid + 256 * i;
        cp16(shB0 + lin * 4, Wblob + lin, 16);
    }
    asm volatile("cp.async.commit_group;");
    asm volatile("cp.async.wait_group 0;");
    __syncthreads();

    if (ADD_PE) {
        int c4 = (tid & 31) << 2;
        float4 pv = *reinterpret_cast<const float4*>(pe + c4);
#pragma unroll
        for (int i = 0; i < 16; i++) {
            int r = (tid + 256 * i) >> 5;
            float4 v = *reinterpret_cast<float4*>(shA + r * AST + c4);
            v.x += pv.x; v.y += pv.y; v.z += pv.z; v.w += pv.w;
            *reinterpret_cast<float4*>(shA + r * AST + c4) = v;
        }
        __syncthreads();
    }

    for (int c = 0; c < CHUNKS; c++) {
        if (c + 1 < CHUNKS) {
            float* nb = ((c + 1) & 1) ? shB1 : shB0;
            const float4* src = Wblob + (size_t)(c + 1) * 4096;
#pragma unroll
            for (int i = 0; i < 16; i++) {
                int lin = tid + 256 * i;
                cp16(nb + lin * 4, src + lin, 16);
            }
            asm volatile("cp.async.commit_group;");
        }

        const float* shB = (c & 1) ? shB1 : shB0;
        float4 acc[8];
#pragma unroll
        for (int nt = 0; nt < 8; nt++) acc[nt] = make_float4(0.f, 0.f, 0.f, 0.f);

#pragma unroll 2
        for (int ks = 0; ks < 16; ks++) {
            int ka = ks * 8 + (lane & 3);
            const float* ap = shA + (wm + g) * AST + ka;
            float a0 = ap[0], a2 = ap[4];
            float a1 = ap[8 * AST], a3 = ap[8 * AST + 4];
            unsigned h0, l0, h1, l1, h2, l2, h3, l3;
            split_tf32(a0, h0, l0); split_tf32(a1, h1, l1);
            split_tf32(a2, h2, l2); split_tf32(a3, h3, l3);
            const uint4* bp = reinterpret_cast<const uint4*>(shB) + ks * 256 + lane;
#pragma unroll
            for (int nt = 0; nt < 8; nt++) {
                uint4 b = bp[nt * 32];
                mma_tf32(acc[nt], h0, h1, h2, h3, b.x, b.y);
                mma_tf32(acc[nt], h0, h1, h2, h3, b.z, b.w);
                mma_tf32(acc[nt], l0, l1, l2, l3, b.x, b.y);
            }
        }

        int r1 = row0 + wm + g, r2 = r1 + 8;
        int colb = c * 64 + 2 * (lane & 3);
        if (colb < HC) {
#pragma unroll
            for (int nt = 0; nt < 8; nt++) {
                int col = colb + nt * 8;
                if (r1 < nrows)
                    *reinterpret_cast<__half2*>(outH + (size_t)r1 * HC + col) =
                        __floats2half2_rn(acc[nt].x, acc[nt].y);
                if (r2 < nrows)
                    *reinterpret_cast<__half2*>(outH + (size_t)r2 * HC + col) =
                        __floats2half2_rn(acc[nt].z, acc[nt].w);
            }
        } else {
#pragma unroll
            for (int nt = 0; nt < 8; nt++) {
                int col = colb - HC + nt * 8;
                if (r1 < nrows)
                    *reinterpret_cast<float2*>(outF + (size_t)r1 * (N - HC) + col) =
                        make_float2(acc[nt].x, acc[nt].y);
                if (r2 < nrows)
                    *reinterpret_cast<float2*>(outF + (size_t)r2 * (N - HC) + col) =
                        make_float2(acc[nt].z, acc[nt].w);
            }
        }

        asm volatile("cp.async.wait_group 0;");
        __syncthreads();
    }
}

// ---------------- layer-0 gather+combine: warp per node (fp16 t) -----------
__global__ __launch_bounds__(256) void gather0_kernel(
    const __half* __restrict__ t,
    const int* __restrict__ degi, const int2* __restrict__ egi,
    const int* __restrict__ dego, const int2* __restrict__ ego,
    const float* __restrict__ bsum,
    const float* __restrict__ cin, const float* __restrict__ cout,
    const float* __restrict__ x, const float* __restrict__ pe,
    float* __restrict__ h1, int n)
{
    int node = (blockIdx.x * 256 + threadIdx.x) >> 5;
    int lane = threadIdx.x & 31;
    if (node >= n) return;

    float4 ic = make_float4(0.f, 0.f, 0.f, 0.f);
    float4 oc = make_float4(0.f, 0.f, 0.f, 0.f);

    int d = min(degi[node], CAP);
    const int2* eb = egi + node * CAP;
#pragma unroll 4
    for (int k = 0; k < d; k++) {
        int2 ed = __ldg(eb + k);
        float w = __int_as_float(ed.y);
        float2 raw = *reinterpret_cast<const float2*>(t + (size_t)ed.x * 256 + lane * 4);
        float2 a = __half22float2(*reinterpret_cast<const __half2*>(&raw.x));
        float2 b = __half22float2(*reinterpret_cast<const __half2*>(&raw.y));
        ic.x += w * a.x; ic.y += w * a.y; ic.z += w * b.x; ic.w += w * b.y;
    }
    d = min(dego[node], CAP);
    eb = ego + node * CAP;
#pragma unroll 4
    for (int k = 0; k < d; k++) {
        int2 ed = __ldg(eb + k);
        float w = __int_as_float(ed.y);
        float2 raw = *reinterpret_cast<const float2*>(t + (size_t)ed.x * 256 + 128 + lane * 4);
        float2 a = __half22float2(*reinterpret_cast<const __half2*>(&raw.x));
        float2 b = __half22float2(*reinterpret_cast<const __half2*>(&raw.y));
        oc.x += w * a.x; oc.y += w * a.y; oc.z += w * b.x; oc.w += w * b.y;
    }

    float ci = __ldg(cin + node), co = __ldg(cout + node);
    float4 bi = *reinterpret_cast<const float4*>(bsum + lane * 4);
    float4 bo = *reinterpret_cast<const float4*>(bsum + 128 + lane * 4);
    float4 r  = *reinterpret_cast<const float4*>(x + (size_t)node * 128 + lane * 4);
    float4 pv = *reinterpret_cast<const float4*>(pe + lane * 4);
    r.x += pv.x; r.y += pv.y; r.z += pv.z; r.w += pv.w;
    float4 o;
    o.x = tanhf(ci * (ic.x + bi.x) + co * (oc.x + bo.x) + r.x);
    o.y = tanhf(ci * (ic.y + bi.y) + co * (oc.y + bo.y) + r.y);
    o.z = tanhf(ci * (ic.z + bi.z) + co * (oc.z + bo.z) + r.z);
    o.w = tanhf(ci * (ic.w + bi.w) + co * (oc.w + bo.w) + r.w);
    *reinterpret_cast<float4*>(h1 + (size_t)node * 128 + lane * 4) = o;
}

// ---------------- layer-1 gather+combine (fp16 u stride 128, fp32 res) -----
__global__ __launch_bounds__(256) void gather1_kernel(
    const __half* __restrict__ u, const float* __restrict__ res,
    const int* __restrict__ degi, const int2* __restrict__ egi,
    const int* __restrict__ dego, const int2* __restrict__ ego,
    const float* __restrict__ bsum,
    const float* __restrict__ cin, const float* __restrict__ cout,
    float* __restrict__ h2, int n)
{
    int node = (blockIdx.x * 256 + threadIdx.x) >> 5;
    int lane = threadIdx.x & 31;
    if (node >= n) return;

    float2 ic = make_float2(0.f, 0.f);
    float2 oc = make_float2(0.f, 0.f);

    int d = min(degi[node], CAP);
    const int2* eb = egi + node * CAP;
#pragma unroll 4
    for (int k = 0; k < d; k++) {
        int2 ed = __ldg(eb + k);
        float w = __int_as_float(ed.y);
        float2 v = __half22float2(*reinterpret_cast<const __half2*>(u + (size_t)ed.x * 128 + lane * 2));
        ic.x += w * v.x; ic.y += w * v.y;
    }
    d = min(dego[node], CAP);
    eb = ego + node * CAP;
#pragma unroll 4
    for (int k = 0; k < d; k++) {
        int2 ed = __ldg(eb + k);
        float w = __int_as_float(ed.y);
        float2 v = __half22float2(*reinterpret_cast<const __half2*>(u + (size_t)ed.x * 128 + 64 + lane * 2));
        oc.x += w * v.x; oc.y += w * v.y;
    }

    float ci = __ldg(cin + node), co = __ldg(cout + node);
    float2 bi = *reinterpret_cast<const float2*>(bsum + 256 + lane * 2);
    float2 bo = *reinterpret_cast<const float2*>(bsum + 320 + lane * 2);
    float2 rb = *reinterpret_cast<const float2*>(bsum + 384 + lane * 2);
    float2 r  = *reinterpret_cast<const float2*>(res + (size_t)node * 64 + lane * 2);
    float2 o;
    o.x = tanhf(ci * (ic.x + bi.x) + co * (oc.x + bo.x) + r.x + rb.x);
    o.y = tanhf(ci * (ic.y + bi.y) + co * (oc.y + bo.y) + r.y + rb.y);
    *reinterpret_cast<float2*>(h2 + (size_t)node * 64 + lane * 2) = o;
}

// ---------------- decoder: tensor GEMM + in-register log_softmax + emb -----
__global__ __launch_bounds__(256) void dec_kernel(
    const float* __restrict__ h2, const float4* __restrict__ Wblob,
    const float* __restrict__ bias, float* __restrict__ logp,
    float* __restrict__ emb, int nrows)
{
    constexpr int AST = 68;
    extern __shared__ float smem[];
    float* shA = smem;                 // 128 * 68 floats
    float* shB = smem + 128 * AST;     // 16384 floats (4096 float4)

    const int tid  = threadIdx.x;
    const int lane = tid & 31;
    const int wm   = (tid >> 5) * 16;
    const int g    = lane >> 2;
    const int q    = lane & 3;
    const int row0 = blockIdx.x * 128;

#pragma unroll
    for (int i = 0; i < 8; i++) {
        int lin = tid + 256 * i;
        int r = lin >> 4, c4 = (lin & 15) << 2;
        int sz = (row0 + r < nrows) ? 16 : 0;
        cp16(shA + r * AST + c4, h2 + (size_t)(row0 + r) * 64 + c4, sz);
    }
#pragma unroll
    for (int i = 0; i < 16; i++) {
        int lin = tid + 256 * i;
        cp16(shB + lin * 4, Wblob + lin, 16);
    }
    asm volatile("cp.async.commit_group;");
    asm volatile("cp.async.wait_group 0;");
    __syncthreads();

    float4 acc[2][8];
#pragma unroll
    for (int c = 0; c < 2; c++)
#pragma unroll
        for (int nt = 0; nt < 8; nt++) acc[c][nt] = make_float4(0.f, 0.f, 0.f, 0.f);

#pragma unroll
    for (int c = 0; c < 2; c++) {
#pragma unroll
        for (int ks = 0; ks < 8; ks++) {
            int ka = ks * 8 + q;
            const float* ap = shA + (wm + g) * AST + ka;
            float a0 = ap[0], a2 = ap[4];
            float a1 = ap[8 * AST], a3 = ap[8 * AST + 4];
            unsigned h0, l0, h1, l1, h2r, l2, h3, l3;
            split_tf32(a0, h0, l0); split_tf32(a1, h1, l1);
            split_tf32(a2, h2r, l2); split_tf32(a3, h3, l3);
            const uint4* bp = reinterpret_cast<const uint4*>(shB) + c * 2048 + ks * 256 + lane;
#pragma unroll
            for (int nt = 0; nt < 8; nt++) {
                uint4 b = bp[nt * 32];
                mma_tf32(acc[c][nt], h0, h1, h2r, h3, b.x, b.y);
                mma_tf32(acc[c][nt], h0, h1, h2r, h3, b.z, b.w);
                mma_tf32(acc[c][nt], l0, l1, l2, l3, b.x, b.y);
            }
        }
    }

    int r1 = row0 + wm + g, r2 = r1 + 8;

    float m1 = -1e30f, m2 = -1e30f;
#pragma unroll
    for (int c = 0; c < 2; c++)
#pragma unroll
        for (int nt = 0; nt < 8; nt++) {
            float2 bb = *reinterpret_cast<const float2*>(bias + c * 64 + nt * 8 + 2 * q);
            acc[c][nt].x += bb.x; acc[c][nt].y += bb.y;
            acc[c][nt].z += bb.x; acc[c][nt].w += bb.y;
            m1 = fmaxf(m1, fmaxf(acc[c][nt].x, acc[c][nt].y));
            m2 = fmaxf(m2, fmaxf(acc[c][nt].z, acc[c][nt].w));
        }
    m1 = fmaxf(m1, __shfl_xor_sync(0xffffffffu, m1, 1));
    m1 = fmaxf(m1, __shfl_xor_sync(0xffffffffu, m1, 2));
    m2 = fmaxf(m2, __shfl_xor_sync(0xffffffffu, m2, 1));
    m2 = fmaxf(m2, __shfl_xor_sync(0xffffffffu, m2, 2));

    float s1 = 0.f, s2 = 0.f;
#pragma unroll
    for (int c = 0; c < 2; c++)
#pragma unroll
        for (int nt = 0; nt < 8; nt++) {
            s1 += expf(acc[c][nt].x - m1) + expf(acc[c][nt].y - m1);
            s2 += expf(acc[c][nt].z - m2) + expf(acc[c][nt].w - m2);
        }
    s1 += __shfl_xor_sync(0xffffffffu, s1, 1);
    s1 += __shfl_xor_sync(0xffffffffu, s1, 2);
    s2 += __shfl_xor_sync(0xffffffffu, s2, 1);
    s2 += __shfl_xor_sync(0xffffffffu, s2, 2);
    float lse1 = m1 + logf(s1), lse2 = m2 + logf(s2);

#pragma unroll
    for (int c = 0; c < 2; c++)
#pragma unroll
        for (int nt = 0; nt < 8; nt++) {
            int col = c * 64 + nt * 8 + 2 * q;
            if (r1 < nrows)
                *reinterpret_cast<float2*>(logp + (size_t)r1 * CLS + col) =
                    make_float2(acc[c][nt].x - lse1, acc[c][nt].y - lse1);
            if (r2 < nrows)
                *reinterpret_cast<float2*>(logp + (size_t)r2 * CLS + col) =
                    make_float2(acc[c][nt].z - lse2, acc[c][nt].w - lse2);
        }

    const float* ar1 = shA + (wm + g) * AST;
    const float* ar2 = ar1 + 8 * AST;
    float4 v1[4], v2[4];
    float sq1 = 0.f, sq2 = 0.f;
#pragma unroll
    for (int j = 0; j < 4; j++) {
        v1[j] = *reinterpret_cast<const float4*>(ar1 + q * 16 + j * 4);
        v2[j] = *reinterpret_cast<const float4*>(ar2 + q * 16 + j * 4);
        sq1 += v1[j].x * v1[j].x + v1[j].y * v1[j].y + v1[j].z * v1[j].z + v1[j].w * v1[j].w;
        sq2 += v2[j].x * v2[j].x + v2[j].y * v2[j].y + v2[j].z * v2[j].z + v2[j].w * v2[j].w;
    }
    sq1 += __shfl_xor_sync(0xffffffffu, sq1, 1);
    sq1 += __shfl_xor_sync(0xffffffffu, sq1, 2);
    sq2 += __shfl_xor_sync(0xffffffffu, sq2, 1);
    sq2 += __shfl_xor_sync(0xffffffffu, sq2, 2);
    float inv1 = 1.f / (sqrtf(sq1) + 1e-12f);
    float inv2 = 1.f / (sqrtf(sq2) + 1e-12f);
#pragma unroll
    for (int j = 0; j < 4; j++) {
        if (r1 < nrows)
            *reinterpret_cast<float4*>(emb + (size_t)r1 * 64 + q * 16 + j * 4) =
                make_float4(v1[j].x * inv1, v1[j].y * inv1, v1[j].z * inv1, v1[j].w * inv1);
        if (r2 < nrows)
            *reinterpret_cast<float4*>(emb + (size_t)r2 * 64 + q * 16 + j * 4) =
                make_float4(v2[j].x * inv2, v2[j].y * inv2, v2[j].z * inv2, v2[j].w * inv2);
    }
}

// ---------------- host ----------------
extern "C" void kernel_launch(void* const* d_in, const int* in_sizes, int n_in,
                              void* d_out, int out_size)
{
    const float* x      = (const float*)d_in[0];
    const int*   ei_in  = (const int*)d_in[1];
    const float* ew_in  = (const float*)d_in[2];
    const int*   ei_out = (const int*)d_in[3];
    const float* ew_out = (const float*)d_in[4];
    const float* pe     = (const float*)d_in[5];

    const float* Wmi0 = (const float*)d_in[6];
    const float* Wmo0 = (const float*)d_in[7];
    const float* Ws0  = (const float*)d_in[8];
    const float* bmi0 = (const float*)d_in[9];
    const float* bmo0 = (const float*)d_in[10];
    const float* bsi0 = (const float*)d_in[11];
    const float* bso0 = (const float*)d_in[12];
    const float* cin0 = (const float*)d_in[13];
    const float* cout0= (const float*)d_in[14];

    const float* Wmi1 = (const float*)d_in[15];
    const float* Wmo1 = (const float*)d_in[16];
    const float* Ws1  = (const float*)d_in[17];
    const float* bmi1 = (const float*)d_in[18];
    const float* bmo1 = (const float*)d_in[19];
    const float* bsi1 = (const float*)d_in[20];
    const float* bso1 = (const float*)d_in[21];
    const float* cin1 = (const float*)d_in[22];
    const float* cout1= (const float*)d_in[23];

    const float* resW = (const float*)d_in[24];
    const float* resb = (const float*)d_in[25];
    const float* decW = (const float*)d_in[26];
    const float* decb = (const float*)d_in[27];

    __half *t, *u;
    float *res, *h1, *h2, *bsum;
    float4 *blob0, *blob1, *blob2;
    int *deg_in, *deg_out;
    int2 *edge_in, *edge_out;
    cudaGetSymbolAddress((void**)&t,   g_t);
    cudaGetSymbolAddress((void**)&u,   g_u);
    cudaGetSymbolAddress((void**)&res, g_res);
    cudaGetSymbolAddress((void**)&h1,  g_h1);
    cudaGetSymbolAddress((void**)&h2,  g_h2);
    cudaGetSymbolAddress((void**)&blob0, g_blob0);
    cudaGetSymbolAddress((void**)&blob1, g_blob1);
    cudaGetSymbolAddress((void**)&blob2, g_blob2);
    cudaGetSymbolAddress((void**)&bsum,g_bsum);
    cudaGetSymbolAddress((void**)&deg_in,  g_deg_in);
    cudaGetSymbolAddress((void**)&deg_out, g_deg_out);
    cudaGetSymbolAddress((void**)&edge_in, g_edge_in);
    cudaGetSymbolAddress((void**)&edge_out,g_edge_out);

    const int N = NN, E = EE, TPB = 256;
    const int SMEM_BYTES = (128 * 132 + 2 * 16384) * 4;
    const int SMEM_DEC   = (128 * 68 + 16384) * 4;

    static cudaStream_t s2 = nullptr;
    static cudaEvent_t ev0 = nullptr, ev2 = nullptr;
    if (!s2) {
        cudaStreamCreateWithFlags(&s2, cudaStreamNonBlocking);
        cudaEventCreateWithFlags(&ev0, cudaEventDisableTiming);
        cudaEventCreateWithFlags(&ev2, cudaEventDisableTiming);
        cudaFuncSetAttribute((const void*)tgemm_kernel<256, 256, true>,
                             cudaFuncAttributeMaxDynamicSharedMemorySize, SMEM_BYTES);
        cudaFuncSetAttribute((const void*)tgemm_kernel<192, 128, false>,
                             cudaFuncAttributeMaxDynamicSharedMemorySize, SMEM_BYTES);
        cudaFuncSetAttribute((const void*)dec_kernel,
                             cudaFuncAttributeMaxDynamicSharedMemorySize, SMEM_DEC);
    }

    // fork edge-bucket branch onto s2 (no count/scan — direct bucket scatter)
    cudaEventRecord(ev0, 0);
    cudaStreamWaitEvent(s2, ev0, 0);
    detect_kernel<<<(N + TPB - 1) / TPB, TPB, 0, s2>>>(ei_in, deg_in, deg_out, N);
    scatter_dual_kernel<<<(2 * E + TPB - 1) / TPB, TPB, 0, s2>>>(
        ei_in, ew_in, ei_out, ew_out, deg_in, deg_out, edge_in, edge_out, E);
    cudaEventRecord(ev2, s2);

    // main branch: weight prep + layer-0 GEMM (PE folded into A staging)
    prep_kernel<<<(16384 + 12288 + 4096 + 448 + TPB - 1) / TPB, TPB>>>(
        Wmi0, Wmo0, Ws0, Wmi1, Wmo1, Ws1, resW, decW,
        bmi0, bsi0, bmo0, bso0, bmi1, bsi1, bmo1, bso1, resb,
        blob0, blob1, blob2, bsum);

    const int GBLK = (N + 127) / 128;
    tgemm_kernel<256, 256, true><<<GBLK, 256, SMEM_BYTES>>>(x, pe, blob0, t, nullptr, N);

    // join: gather0 needs buckets and t
    cudaStreamWaitEvent(0, ev2, 0);
    gather0_kernel<<<(N * 32 + TPB - 1) / TPB, TPB>>>(
        t, deg_in, edge_in, deg_out, edge_out,
        bsum, cin0, cout0, x, pe, h1, N);

    // layer 1 (residual slice stored fp32)
    tgemm_kernel<192, 128, false><<<GBLK, 256, SMEM_BYTES>>>(h1, pe, blob1, u, res, N);
    gather1_kernel<<<(N * 32 + TPB - 1) / TPB, TPB>>>(
        u, res, deg_in, edge_in, deg_out, edge_out,
        bsum, cin1, cout1, h2, N);

    // fused decoder: tensor GEMM + log_softmax + L2-normalized emb
    float* out = (float*)d_out;
    dec_kernel<<<GBLK, 256, SMEM_DEC>>>(h2, blob2, decb, out, out + (size_t)N * CLS, N);
}

// round 9
// speedup vs baseline: 1.4460x; 1.2182x over previous
#include <cuda_runtime.h>
#include <cuda_fp16.h>
#include <cuda_bf16.h>
#include <math.h>

#define NN 50000
#define EE 800000
#define CLS 128
#define CAP 64

// ---------------- static device scratch ----------------
__device__ __half g_t [NN * 256];
__device__ __half g_u [NN * 128];
__device__ float g_res[NN * 64];
__device__ float g_h1[NN * 128];
__device__ float g_h2[NN * 64];
__device__ uint4 g_blob0[8192];    // layer0 W: K=128,N=256, bf16 hi/lo frag order
__device__ uint4 g_blob1[6144];    // layer1 W: K=128,N=192 (incl res)
__device__ uint4 g_blob2[2048];    // decoder W: K=64,N=128
__device__ float g_bsum[448];
__device__ int   g_deg_in[NN];
__device__ int   g_deg_out[NN];
__device__ int2  g_edge_in [NN * CAP];  // per-node bucket: (src, weight bits)
__device__ int2  g_edge_out[NN * CAP];
__device__ int   g_is64;

// ---------------- bf16 hi/lo helpers ----------------
__device__ __forceinline__ void split_bf16(float x, float y, unsigned& hi, unsigned& lo) {
    __nv_bfloat162 h = __floats2bfloat162_rn(x, y);
    float2 hf = __bfloat1622float2(h);
    __nv_bfloat162 l = __floats2bfloat162_rn(x - hf.x, y - hf.y);
    hi = *reinterpret_cast<unsigned*>(&h);
    lo = *reinterpret_cast<unsigned*>(&l);
}

__device__ __forceinline__ void mma_bf16(float4& d,
    unsigned a0, unsigned a1, unsigned a2, unsigned a3,
    unsigned b0, unsigned b1)
{
    asm volatile(
        "mma.sync.aligned.m16n8k16.row.col.f32.bf16.bf16.f32 "
        "{%0,%1,%2,%3},{%4,%5,%6,%7},{%8,%9},{%0,%1,%2,%3};"
        : "+f"(d.x), "+f"(d.y), "+f"(d.z), "+f"(d.w)
        : "r"(a0), "r"(a1), "r"(a2), "r"(a3), "r"(b0), "r"(b1));
}

__device__ __forceinline__ void cp16(void* smem_dst, const void* gsrc, int sz) {
    unsigned du = (unsigned)__cvta_generic_to_shared(smem_dst);
    asm volatile("cp.async.cg.shared.global [%0], [%1], 16, %2;"
                 :: "r"(du), "l"(gsrc), "r"(sz));
}

// ---------------- misc small kernels ----------------
__global__ void detect_kernel(const int* __restrict__ ei, int* __restrict__ da,
                              int* __restrict__ db, int n) {
    if (blockIdx.x == 0 && threadIdx.x == 0) {
        int z = 0;
        for (int i = 1; i < 129; i += 2) z |= ei[i];
        g_is64 = (z == 0) ? 1 : 0;
    }
    int i = blockIdx.x * blockDim.x + threadIdx.x;
    if (i < n) { da[i] = 0; db[i] = 0; }
}

// build bf16 hi/lo frag-ordered weight blobs + combined biases
__global__ void prep_kernel(
    const float* __restrict__ Wmi0, const float* __restrict__ Wmo0, const float* __restrict__ Ws0,
    const float* __restrict__ Wmi1, const float* __restrict__ Wmo1, const float* __restrict__ Ws1,
    const float* __restrict__ resW, const float* __restrict__ decW,
    const float* __restrict__ bmi0, const float* __restrict__ bsi0,
    const float* __restrict__ bmo0, const float* __restrict__ bso0,
    const float* __restrict__ bmi1, const float* __restrict__ bsi1,
    const float* __restrict__ bmo1, const float* __restrict__ bso1,
    const float* __restrict__ resb,
    uint4* __restrict__ blob0, uint4* __restrict__ blob1,
    uint4* __restrict__ blob2, float* __restrict__ bsum)
{
    int i = blockIdx.x * blockDim.x + threadIdx.x;
    if (i < 8192) {
        // layer0: index = ((c*8 + ks)*8 + nt)*32 + lane, c<4, K=128, N=256
        int lane = i & 31; int j = i >> 5;
        int nt = j & 7; j >>= 3;
        int ks = j & 7; j >>= 3;
        int c = j;
        int q = lane & 3;
        int n = c * 64 + nt * 8 + (lane >> 2);
        int nn = n & 127;
        int k0 = ks * 16 + 2 * q;
        float w[4];
#pragma unroll
        for (int m = 0; m < 4; m++) {
            int k = k0 + (m >> 1) * 8 + (m & 1);
            w[m] = Ws0[k * 128 + nn] + ((n < 128) ? Wmi0[k * 128 + n] : Wmo0[k * 128 + n - 128]);
        }
        uint4 o;
        split_bf16(w[0], w[1], o.x, o.z);
        split_bf16(w[2], w[3], o.y, o.w);
        blob0[i] = o;
        return;
    }
    int i1 = i - 8192;
    if (i1 < 6144) {
        // layer1: c<3 (0-63 in, 64-127 out, 128-191 res), K=128
        int lane = i1 & 31; int j = i1 >> 5;
        int nt = j & 7; j >>= 3;
        int ks = j & 7; j >>= 3;
        int c = j;
        int q = lane & 3;
        int n = c * 64 + nt * 8 + (lane >> 2);
        int k0 = ks * 16 + 2 * q;
        float w[4];
#pragma unroll
        for (int m = 0; m < 4; m++) {
            int k = k0 + (m >> 1) * 8 + (m & 1);
            if (n < 128) {
                int nn = n & 63;
                w[m] = Ws1[k * 64 + nn] + ((n < 64) ? Wmi1[k * 64 + n] : Wmo1[k * 64 + n - 64]);
            } else {
                w[m] = resW[k * 64 + n - 128];
            }
        }
        uint4 o;
        split_bf16(w[0], w[1], o.x, o.z);
        split_bf16(w[2], w[3], o.y, o.w);
        blob1[i1] = o;
        return;
    }
    int i2 = i1 - 6144;
    if (i2 < 2048) {
        // decoder: c<2, K=64 -> ks<4: index = ((c*4 + ks)*8 + nt)*32 + lane
        int lane = i2 & 31; int j = i2 >> 5;
        int nt = j & 7; j >>= 3;
        int ks = j & 3; j >>= 2;
        int c = j;
        int q = lane & 3;
        int n = c * 64 + nt * 8 + (lane >> 2);
        int k0 = ks * 16 + 2 * q;
        float w[4];
#pragma unroll
        for (int m = 0; m < 4; m++) {
            int k = k0 + (m >> 1) * 8 + (m & 1);
            w[m] = decW[k * 128 + n];
        }
        uint4 o;
        split_bf16(w[0], w[1], o.x, o.z);
        split_bf16(w[2], w[3], o.y, o.w);
        blob2[i2] = o;
        return;
    }
    int i3 = i2 - 2048;
    if (i3 < 128)       bsum[i3] = bmi0[i3] + bsi0[i3];
    else if (i3 < 256)  bsum[i3] = bmo0[i3 - 128] + bso0[i3 - 128];
    else if (i3 < 320)  bsum[i3] = bmi1[i3 - 256] + bsi1[i3 - 256];
    else if (i3 < 384)  bsum[i3] = bmo1[i3 - 320] + bso1[i3 - 320];
    else if (i3 < 448)  bsum[i3] = resb[i3 - 384];
}

// ---------------- direct bucket scatter (no count/scan) --------------------
__global__ void scatter_dual_kernel(
    const int* __restrict__ ei_a, const float* __restrict__ ew_a,
    const int* __restrict__ ei_b, const float* __restrict__ ew_b,
    int* __restrict__ deg_a, int* __restrict__ deg_b,
    int2* __restrict__ edge_a, int2* __restrict__ edge_b, int E)
{
    int e = blockIdx.x * blockDim.x + threadIdx.x;
    int which = (e >= E);
    int idx = which ? e - E : e;
    if (idx >= E) return;
    const int* ei   = which ? ei_b : ei_a;
    const float* ew = which ? ew_b : ew_a;
    int* deg   = which ? deg_b : deg_a;
    int2* edge = which ? edge_b : edge_a;
    int src, tgt;
    if (g_is64) {
        const long long* p = (const long long*)ei;
        src = (int)p[idx]; tgt = (int)p[E + idx];
    } else {
        src = ei[idx]; tgt = ei[E + idx];
    }
    int pos = atomicAdd(deg + tgt, 1);
    if (pos < CAP)
        edge[tgt * CAP + pos] = make_int2(src, __float_as_int(ew[idx]));
}

// ---------------- bf16 hi/lo tensor GEMM: one 64-col chunk per CTA ---------
// grid = (row blocks, chunks). fp16 out for chunks with colbase < HC, else fp32.
template<int N, int HC, bool ADD_PE>
__global__ __launch_bounds__(256) void tgemm_kernel(
    const float* __restrict__ H, const float* __restrict__ pe,
    const uint4* __restrict__ Wblob, __half* __restrict__ outH,
    float* __restrict__ outF, int nrows)
{
    constexpr int K = 128;
    constexpr int AST = K + 4;
    extern __shared__ float smem[];
    float* shA = smem;                               // 128*132 floats (66 KB)
    uint4* shB = reinterpret_cast<uint4*>(smem + 128 * AST);  // 2048 uint4 (32 KB)

    const int tid  = threadIdx.x;
    const int lane = tid & 31;
    const int wm   = (tid >> 5) * 16;
    const int g    = lane >> 2;
    const int q    = lane & 3;
    const int row0 = blockIdx.x * 128;
    const int c    = blockIdx.y;

#pragma unroll
    for (int i = 0; i < 16; i++) {
        int lin = tid + 256 * i;
        int r = lin >> 5, c4 = (lin & 31) << 2;
        int sz = (row0 + r < nrows) ? 16 : 0;
        cp16(shA + r * AST + c4, H + (size_t)(row0 + r) * K + c4, sz);
    }
    const uint4* bsrc = Wblob + (size_t)c * 2048;
#pragma unroll
    for (int i = 0; i < 8; i++) {
        int lin = tid + 256 * i;
        cp16(shB + lin, bsrc + lin, 16);
    }
    asm volatile("cp.async.commit_group;");
    asm volatile("cp.async.wait_group 0;");
    __syncthreads();

    if (ADD_PE) {
        int c4 = (tid & 31) << 2;
        float4 pv = *reinterpret_cast<const float4*>(pe + c4);
#pragma unroll
        for (int i = 0; i < 16; i++) {
            int r = (tid + 256 * i) >> 5;
            float4 v = *reinterpret_cast<float4*>(shA + r * AST + c4);
            v.x += pv.x; v.y += pv.y; v.z += pv.z; v.w += pv.w;
            *reinterpret_cast<float4*>(shA + r * AST + c4) = v;
        }
        __syncthreads();
    }

    float4 acc[8];
#pragma unroll
    for (int nt = 0; nt < 8; nt++) acc[nt] = make_float4(0.f, 0.f, 0.f, 0.f);

#pragma unroll
    for (int ks = 0; ks < 8; ks++) {
        int k0 = ks * 16 + 2 * q;
        const float* ap = shA + (wm + g) * AST;
        float2 vA = *reinterpret_cast<const float2*>(ap + k0);             // row g,   k01
        float2 vB = *reinterpret_cast<const float2*>(ap + k0 + 8);         // row g,   k89
        float2 vC = *reinterpret_cast<const float2*>(ap + 8 * AST + k0);   // row g+8, k01
        float2 vD = *reinterpret_cast<const float2*>(ap + 8 * AST + k0 + 8);
        unsigned ah0, al0, ah1, al1, ah2, al2, ah3, al3;
        split_bf16(vA.x, vA.y, ah0, al0);
        split_bf16(vC.x, vC.y, ah1, al1);
        split_bf16(vB.x, vB.y, ah2, al2);
        split_bf16(vD.x, vD.y, ah3, al3);
        const uint4* bp = shB + ks * 256 + lane;
#pragma unroll
        for (int nt = 0; nt < 8; nt++) {
            uint4 b = bp[nt * 32];
            mma_bf16(acc[nt], ah0, ah1, ah2, ah3, b.x, b.y);  // hi*hi
            mma_bf16(acc[nt], ah0, ah1, ah2, ah3, b.z, b.w);  // hi*lo
            mma_bf16(acc[nt], al0, al1, al2, al3, b.x, b.y);  // lo*hi
        }
    }

    int r1 = row0 + wm + g, r2 = r1 + 8;
    int colb = c * 64 + 2 * q;
    if (colb < HC) {
#pragma unroll
        for (int nt = 0; nt < 8; nt++) {
            int col = colb + nt * 8;
            if (r1 < nrows)
                *reinterpret_cast<__half2*>(outH + (size_t)r1 * HC + col) =
                    __floats2half2_rn(acc[nt].x, acc[nt].y);
            if (r2 < nrows)
                *reinterpret_cast<__half2*>(outH + (size_t)r2 * HC + col) =
                    __floats2half2_rn(acc[nt].z, acc[nt].w);
        }
    } else {
#pragma unroll
        for (int nt = 0; nt < 8; nt++) {
            int col = colb - HC + nt * 8;
            if (r1 < nrows)
                *reinterpret_cast<float2*>(outF + (size_t)r1 * (N - HC) + col) =
                    make_float2(acc[nt].x, acc[nt].y);
            if (r2 < nrows)
                *reinterpret_cast<float2*>(outF + (size_t)r2 * (N - HC) + col) =
                    make_float2(acc[nt].z, acc[nt].w);
        }
    }
}

// ---------------- layer-0 gather+combine: warp per node (fp16 t) -----------
__global__ __launch_bounds__(256) void gather0_kernel(
    const __half* __restrict__ t,
    const int* __restrict__ degi, const int2* __restrict__ egi,
    const int* __restrict__ dego, const int2* __restrict__ ego,
    const float* __restrict__ bsum,
    const float* __restrict__ cin, const float* __restrict__ cout,
    const float* __restrict__ x, const float* __restrict__ pe,
    float* __restrict__ h1, int n)
{
    int node = (blockIdx.x * 256 + threadIdx.x) >> 5;
    int lane = threadIdx.x & 31;
    if (node >= n) return;

    float4 ic = make_float4(0.f, 0.f, 0.f, 0.f);
    float4 oc = make_float4(0.f, 0.f, 0.f, 0.f);

    int d = min(degi[node], CAP);
    const int2* eb = egi + node * CAP;
#pragma unroll 4
    for (int k = 0; k < d; k++) {
        int2 ed = __ldg(eb + k);
        float w = __int_as_float(ed.y);
        float2 raw = *reinterpret_cast<const float2*>(t + (size_t)ed.x * 256 + lane * 4);
        float2 a = __half22float2(*reinterpret_cast<const __half2*>(&raw.x));
        float2 b = __half22float2(*reinterpret_cast<const __half2*>(&raw.y));
        ic.x += w * a.x; ic.y += w * a.y; ic.z += w * b.x; ic.w += w * b.y;
    }
    d = min(dego[node], CAP);
    eb = ego + node * CAP;
#pragma unroll 4
    for (int k = 0; k < d; k++) {
        int2 ed = __ldg(eb + k);
        float w = __int_as_float(ed.y);
        float2 raw = *reinterpret_cast<const float2*>(t + (size_t)ed.x * 256 + 128 + lane * 4);
        float2 a = __half22float2(*reinterpret_cast<const __half2*>(&raw.x));
        float2 b = __half22float2(*reinterpret_cast<const __half2*>(&raw.y));
        oc.x += w * a.x; oc.y += w * a.y; oc.z += w * b.x; oc.w += w * b.y;
    }

    float ci = __ldg(cin + node), co = __ldg(cout + node);
    float4 bi = *reinterpret_cast<const float4*>(bsum + lane * 4);
    float4 bo = *reinterpret_cast<const float4*>(bsum + 128 + lane * 4);
    float4 r  = *reinterpret_cast<const float4*>(x + (size_t)node * 128 + lane * 4);
    float4 pv = *reinterpret_cast<const float4*>(pe + lane * 4);
    r.x += pv.x; r.y += pv.y; r.z += pv.z; r.w += pv.w;
    float4 o;
    o.x = tanhf(ci * (ic.x + bi.x) + co * (oc.x + bo.x) + r.x);
    o.y = tanhf(ci * (ic.y + bi.y) + co * (oc.y + bo.y) + r.y);
    o.z = tanhf(ci * (ic.z + bi.z) + co * (oc.z + bo.z) + r.z);
    o.w = tanhf(ci * (ic.w + bi.w) + co * (oc.w + bo.w) + r.w);
    *reinterpret_cast<float4*>(h1 + (size_t)node * 128 + lane * 4) = o;
}

// ---------------- layer-1 gather+combine (fp16 u stride 128, fp32 res) -----
__global__ __launch_bounds__(256) void gather1_kernel(
    const __half* __restrict__ u, const float* __restrict__ res,
    const int* __restrict__ degi, const int2* __restrict__ egi,
    const int* __restrict__ dego, const int2* __restrict__ ego,
    const float* __restrict__ bsum,
    const float* __restrict__ cin, const float* __restrict__ cout,
    float* __restrict__ h2, int n)
{
    int node = (blockIdx.x * 256 + threadIdx.x) >> 5;
    int lane = threadIdx.x & 31;
    if (node >= n) return;

    float2 ic = make_float2(0.f, 0.f);
    float2 oc = make_float2(0.f, 0.f);

    int d = min(degi[node], CAP);
    const int2* eb = egi + node * CAP;
#pragma unroll 4
    for (int k = 0; k < d; k++) {
        int2 ed = __ldg(eb + k);
        float w = __int_as_float(ed.y);
        float2 v = __half22float2(*reinterpret_cast<const __half2*>(u + (size_t)ed.x * 128 + lane * 2));
        ic.x += w * v.x; ic.y += w * v.y;
    }
    d = min(dego[node], CAP);
    eb = ego + node * CAP;
#pragma unroll 4
    for (int k = 0; k < d; k++) {
        int2 ed = __ldg(eb + k);
        float w = __int_as_float(ed.y);
        float2 v = __half22float2(*reinterpret_cast<const __half2*>(u + (size_t)ed.x * 128 + 64 + lane * 2));
        oc.x += w * v.x; oc.y += w * v.y;
    }

    float ci = __ldg(cin + node), co = __ldg(cout + node);
    float2 bi = *reinterpret_cast<const float2*>(bsum + 256 + lane * 2);
    float2 bo = *reinterpret_cast<const float2*>(bsum + 320 + lane * 2);
    float2 rb = *reinterpret_cast<const float2*>(bsum + 384 + lane * 2);
    float2 r  = *reinterpret_cast<const float2*>(res + (size_t)node * 64 + lane * 2);
    float2 o;
    o.x = tanhf(ci * (ic.x + bi.x) + co * (oc.x + bo.x) + r.x + rb.x);
    o.y = tanhf(ci * (ic.y + bi.y) + co * (oc.y + bo.y) + r.y + rb.y);
    *reinterpret_cast<float2*>(h2 + (size_t)node * 64 + lane * 2) = o;
}

// ---------------- decoder: bf16 GEMM + in-register log_softmax + emb -------
__global__ __launch_bounds__(256) void dec_kernel(
    const float* __restrict__ h2, const uint4* __restrict__ Wblob,
    const float* __restrict__ bias, float* __restrict__ logp,
    float* __restrict__ emb, int nrows)
{
    constexpr int AST = 68;
    extern __shared__ float smem[];
    float* shA = smem;                                   // 128*68 floats
    uint4* shB = reinterpret_cast<uint4*>(smem + 128 * AST);  // 2048 uint4

    const int tid  = threadIdx.x;
    const int lane = tid & 31;
    const int wm   = (tid >> 5) * 16;
    const int g    = lane >> 2;
    const int q    = lane & 3;
    const int row0 = blockIdx.x * 128;

#pragma unroll
    for (int i = 0; i < 8; i++) {
        int lin = tid + 256 * i;
        int r = lin >> 4, c4 = (lin & 15) << 2;
        int sz = (row0 + r < nrows) ? 16 : 0;
        cp16(shA + r * AST + c4, h2 + (size_t)(row0 + r) * 64 + c4, sz);
    }
#pragma unroll
    for (int i = 0; i < 8; i++) {
        int lin = tid + 256 * i;
        cp16(shB + lin, Wblob + lin, 16);
    }
    asm volatile("cp.async.commit_group;");
    asm volatile("cp.async.wait_group 0;");
    __syncthreads();

    float4 acc[2][8];
#pragma unroll
    for (int c = 0; c < 2; c++)
#pragma unroll
        for (int nt = 0; nt < 8; nt++) acc[c][nt] = make_float4(0.f, 0.f, 0.f, 0.f);

#pragma unroll
    for (int c = 0; c < 2; c++) {
#pragma unroll
        for (int ks = 0; ks < 4; ks++) {
            int k0 = ks * 16 + 2 * q;
            const float* ap = shA + (wm + g) * AST;
            float2 vA = *reinterpret_cast<const float2*>(ap + k0);
            float2 vB = *reinterpret_cast<const float2*>(ap + k0 + 8);
            float2 vC = *reinterpret_cast<const float2*>(ap + 8 * AST + k0);
            float2 vD = *reinterpret_cast<const float2*>(ap + 8 * AST + k0 + 8);
            unsigned ah0, al0, ah1, al1, ah2, al2, ah3, al3;
            split_bf16(vA.x, vA.y, ah0, al0);
            split_bf16(vC.x, vC.y, ah1, al1);
            split_bf16(vB.x, vB.y, ah2, al2);
            split_bf16(vD.x, vD.y, ah3, al3);
            const uint4* bp = shB + (c * 4 + ks) * 256 + lane;
#pragma unroll
            for (int nt = 0; nt < 8; nt++) {
                uint4 b = bp[nt * 32];
                mma_bf16(acc[c][nt], ah0, ah1, ah2, ah3, b.x, b.y);
                mma_bf16(acc[c][nt], ah0, ah1, ah2, ah3, b.z, b.w);
                mma_bf16(acc[c][nt], al0, al1, al2, al3, b.x, b.y);
            }
        }
    }

    int r1 = row0 + wm + g, r2 = r1 + 8;

    float m1 = -1e30f, m2 = -1e30f;
#pragma unroll
    for (int c = 0; c < 2; c++)
#pragma unroll
        for (int nt = 0; nt < 8; nt++) {
            float2 bb = *reinterpret_cast<const float2*>(bias + c * 64 + nt * 8 + 2 * q);
            acc[c][nt].x += bb.x; acc[c][nt].y += bb.y;
            acc[c][nt].z += bb.x; acc[c][nt].w += bb.y;
            m1 = fmaxf(m1, fmaxf(acc[c][nt].x, acc[c][nt].y));
            m2 = fmaxf(m2, fmaxf(acc[c][nt].z, acc[c][nt].w));
        }
    m1 = fmaxf(m1, __shfl_xor_sync(0xffffffffu, m1, 1));
    m1 = fmaxf(m1, __shfl_xor_sync(0xffffffffu, m1, 2));
    m2 = fmaxf(m2, __shfl_xor_sync(0xffffffffu, m2, 1));
    m2 = fmaxf(m2, __shfl_xor_sync(0xffffffffu, m2, 2));

    float s1 = 0.f, s2 = 0.f;
#pragma unroll
    for (int c = 0; c < 2; c++)
#pragma unroll
        for (int nt = 0; nt < 8; nt++) {
            s1 += expf(acc[c][nt].x - m1) + expf(acc[c][nt].y - m1);
            s2 += expf(acc[c][nt].z - m2) + expf(acc[c][nt].w - m2);
        }
    s1 += __shfl_xor_sync(0xffffffffu, s1, 1);
    s1 += __shfl_xor_sync(0xffffffffu, s1, 2);
    s2 += __shfl_xor_sync(0xffffffffu, s2, 1);
    s2 += __shfl_xor_sync(0xffffffffu, s2, 2);
    float lse1 = m1 + logf(s1), lse2 = m2 + logf(s2);

#pragma unroll
    for (int c = 0; c < 2; c++)
#pragma unroll
        for (int nt = 0; nt < 8; nt++) {
            int col = c * 64 + nt * 8 + 2 * q;
            if (r1 < nrows)
                *reinterpret_cast<float2*>(logp + (size_t)r1 * CLS + col) =
                    make_float2(acc[c][nt].x - lse1, acc[c][nt].y - lse1);
            if (r2 < nrows)
                *reinterpret_cast<float2*>(logp + (size_t)r2 * CLS + col) =
                    make_float2(acc[c][nt].z - lse2, acc[c][nt].w - lse2);
        }

    const float* ar1 = shA + (wm + g) * AST;
    const float* ar2 = ar1 + 8 * AST;
    float4 v1[4], v2[4];
    float sq1 = 0.f, sq2 = 0.f;
#pragma unroll
    for (int j = 0; j < 4; j++) {
        v1[j] = *reinterpret_cast<const float4*>(ar1 + q * 16 + j * 4);
        v2[j] = *reinterpret_cast<const float4*>(ar2 + q * 16 + j * 4);
        sq1 += v1[j].x * v1[j].x + v1[j].y * v1[j].y + v1[j].z * v1[j].z + v1[j].w * v1[j].w;
        sq2 += v2[j].x * v2[j].x + v2[j].y * v2[j].y + v2[j].z * v2[j].z + v2[j].w * v2[j].w;
    }
    sq1 += __shfl_xor_sync(0xffffffffu, sq1, 1);
    sq1 += __shfl_xor_sync(0xffffffffu, sq1, 2);
    sq2 += __shfl_xor_sync(0xffffffffu, sq2, 1);
    sq2 += __shfl_xor_sync(0xffffffffu, sq2, 2);
    float inv1 = 1.f / (sqrtf(sq1) + 1e-12f);
    float inv2 = 1.f / (sqrtf(sq2) + 1e-12f);
#pragma unroll
    for (int j = 0; j < 4; j++) {
        if (r1 < nrows)
            *reinterpret_cast<float4*>(emb + (size_t)r1 * 64 + q * 16 + j * 4) =
                make_float4(v1[j].x * inv1, v1[j].y * inv1, v1[j].z * inv1, v1[j].w * inv1);
        if (r2 < nrows)
            *reinterpret_cast<float4*>(emb + (size_t)r2 * 64 + q * 16 + j * 4) =
                make_float4(v2[j].x * inv2, v2[j].y * inv2, v2[j].z * inv2, v2[j].w * inv2);
    }
}

// ---------------- host ----------------
extern "C" void kernel_launch(void* const* d_in, const int* in_sizes, int n_in,
                              void* d_out, int out_size)
{
    const float* x      = (const float*)d_in[0];
    const int*   ei_in  = (const int*)d_in[1];
    const float* ew_in  = (const float*)d_in[2];
    const int*   ei_out = (const int*)d_in[3];
    const float* ew_out = (const float*)d_in[4];
    const float* pe     = (const float*)d_in[5];

    const float* Wmi0 = (const float*)d_in[6];
    const float* Wmo0 = (const float*)d_in[7];
    const float* Ws0  = (const float*)d_in[8];
    const float* bmi0 = (const float*)d_in[9];
    const float* bmo0 = (const float*)d_in[10];
    const float* bsi0 = (const float*)d_in[11];
    const float* bso0 = (const float*)d_in[12];
    const float* cin0 = (const float*)d_in[13];
    const float* cout0= (const float*)d_in[14];

    const float* Wmi1 = (const float*)d_in[15];
    const float* Wmo1 = (const float*)d_in[16];
    const float* Ws1  = (const float*)d_in[17];
    const float* bmi1 = (const float*)d_in[18];
    const float* bmo1 = (const float*)d_in[19];
    const float* bsi1 = (const float*)d_in[20];
    const float* bso1 = (const float*)d_in[21];
    const float* cin1 = (const float*)d_in[22];
    const float* cout1= (const float*)d_in[23];

    const float* resW = (const float*)d_in[24];
    const float* resb = (const float*)d_in[25];
    const float* decW = (const float*)d_in[26];
    const float* decb = (const float*)d_in[27];

    __half *t, *u;
    float *res, *h1, *h2, *bsum;
    uint4 *blob0, *blob1, *blob2;
    int *deg_in, *deg_out;
    int2 *edge_in, *edge_out;
    cudaGetSymbolAddress((void**)&t,   g_t);
    cudaGetSymbolAddress((void**)&u,   g_u);
    cudaGetSymbolAddress((void**)&res, g_res);
    cudaGetSymbolAddress((void**)&h1,  g_h1);
    cudaGetSymbolAddress((void**)&h2,  g_h2);
    cudaGetSymbolAddress((void**)&blob0, g_blob0);
    cudaGetSymbolAddress((void**)&blob1, g_blob1);
    cudaGetSymbolAddress((void**)&blob2, g_blob2);
    cudaGetSymbolAddress((void**)&bsum,g_bsum);
    cudaGetSymbolAddress((void**)&deg_in,  g_deg_in);
    cudaGetSymbolAddress((void**)&deg_out, g_deg_out);
    cudaGetSymbolAddress((void**)&edge_in, g_edge_in);
    cudaGetSymbolAddress((void**)&edge_out,g_edge_out);

    const int N = NN, E = EE, TPB = 256;
    const int SMEM_GEMM = 128 * 132 * 4 + 2048 * 16;  // 100352 B
    const int SMEM_DEC  = 128 * 68 * 4 + 2048 * 16;   // 67584 B

    static cudaStream_t s2 = nullptr;
    static cudaEvent_t ev0 = nullptr, ev2 = nullptr;
    if (!s2) {
        cudaStreamCreateWithFlags(&s2, cudaStreamNonBlocking);
        cudaEventCreateWithFlags(&ev0, cudaEventDisableTiming);
        cudaEventCreateWithFlags(&ev2, cudaEventDisableTiming);
        cudaFuncSetAttribute((const void*)tgemm_kernel<256, 256, true>,
                             cudaFuncAttributeMaxDynamicSharedMemorySize, SMEM_GEMM);
        cudaFuncSetAttribute((const void*)tgemm_kernel<192, 128, false>,
                             cudaFuncAttributeMaxDynamicSharedMemorySize, SMEM_GEMM);
        cudaFuncSetAttribute((const void*)dec_kernel,
                             cudaFuncAttributeMaxDynamicSharedMemorySize, SMEM_DEC);
    }

    // fork edge-bucket branch onto s2
    cudaEventRecord(ev0, 0);
    cudaStreamWaitEvent(s2, ev0, 0);
    detect_kernel<<<(N + TPB - 1) / TPB, TPB, 0, s2>>>(ei_in, deg_in, deg_out, N);
    scatter_dual_kernel<<<(2 * E + TPB - 1) / TPB, TPB, 0, s2>>>(
        ei_in, ew_in, ei_out, ew_out, deg_in, deg_out, edge_in, edge_out, E);
    cudaEventRecord(ev2, s2);

    // main branch: weight prep + layer-0 GEMM (PE folded into A staging)
    prep_kernel<<<(8192 + 6144 + 2048 + 448 + TPB - 1) / TPB, TPB>>>(
        Wmi0, Wmo0, Ws0, Wmi1, Wmo1, Ws1, resW, decW,
        bmi0, bsi0, bmo0, bso0, bmi1, bsi1, bmo1, bso1, resb,
        blob0, blob1, blob2, bsum);

    const int GBLK = (N + 127) / 128;
    {
        dim3 grid(GBLK, 4);
        tgemm_kernel<256, 256, true><<<grid, 256, SMEM_GEMM>>>(x, pe, blob0, t, nullptr, N);
    }

    // join: gather0 needs buckets and t
    cudaStreamWaitEvent(0, ev2, 0);
    gather0_kernel<<<(N * 32 + TPB - 1) / TPB, TPB>>>(
        t, deg_in, edge_in, deg_out, edge_out,
        bsum, cin0, cout0, x, pe, h1, N);

    // layer 1 (residual slice stored fp32)
    {
        dim3 grid(GBLK, 3);
        tgemm_kernel<192, 128, false><<<grid, 256, SMEM_GEMM>>>(h1, pe, blob1, u, res, N);
    }
    gather1_kernel<<<(N * 32 + TPB - 1) / TPB, TPB>>>(
        u, res, deg_in, edge_in, deg_out, edge_out,
        bsum, cin1, cout1, h2, N);

    // fused decoder: bf16 GEMM + log_softmax + L2-normalized emb
    float* out = (float*)d_out;
    dec_kernel<<<GBLK, 256, SMEM_DEC>>>(h2, blob2, decb, out, out + (size_t)N * CLS, N);
}